// round 1
// baseline (speedup 1.0000x reference)
#include <cuda_runtime.h>
#include <cuda_bf16.h>

// ---------------- problem constants ----------------
#define BATCH 4
#define SEQ   2048
#define CDIM  1024
#define NHEAD 16
#define HDIM  64
#define C3    (3*CDIM)
#define MROWS (BATCH*SEQ)   // 8192

// ---------------- scratch (device globals: allocation-free) ----------------
__device__ float g_qkv[MROWS * C3];   // [8192, 3072]
__device__ float g_y[MROWS * CDIM];   // [8192, 1024]

// =================================================================
// SGEMM with bias: C[M,N] = A[M,K] @ B[K,N] + bias[N]
// 128x128 block tile, BK=16, 256 threads, 8x8 per thread (4+4 split).
// Register-prefetch of next K-tile to hide global latency.
// =================================================================
#define BM 128
#define BN 128
#define BK 16

__global__ __launch_bounds__(256) void sgemm_bias_kernel(
    const float* __restrict__ A, const float* __restrict__ Bm,
    const float* __restrict__ bias, float* __restrict__ C,
    int M, int N, int K)
{
    __shared__ float As[BK][BM];   // A tile transposed: As[k][m]
    __shared__ float Bs[BK][BN];   // B tile natural:   Bs[k][n]

    const int tid = threadIdx.x;
    const int tx = tid & 15;       // 0..15 -> N
    const int ty = tid >> 4;       // 0..15 -> M
    const int m0 = blockIdx.y * BM;
    const int n0 = blockIdx.x * BN;

    // A load mapping (2048 floats = 512 float4 units; 2 units/thread)
    const int au0 = tid, au1 = tid + 256;
    const int ar0 = au0 >> 2, ak0 = (au0 & 3) << 2;
    const int ar1 = au1 >> 2, ak1 = (au1 & 3) << 2;
    // B load mapping
    const int br0 = au0 >> 5, bc0 = (au0 & 31) << 2;
    const int br1 = au1 >> 5, bc1 = (au1 & 31) << 2;

    float4 ra0, ra1, rb0, rb1;

    // load tile 0
    {
        const int kt = 0;
        ra0 = *(const float4*)&A[(m0 + ar0) * K + kt + ak0];
        ra1 = *(const float4*)&A[(m0 + ar1) * K + kt + ak1];
        rb0 = *(const float4*)&Bm[(kt + br0) * N + n0 + bc0];
        rb1 = *(const float4*)&Bm[(kt + br1) * N + n0 + bc1];
    }
    // store tile 0
    As[ak0+0][ar0] = ra0.x; As[ak0+1][ar0] = ra0.y; As[ak0+2][ar0] = ra0.z; As[ak0+3][ar0] = ra0.w;
    As[ak1+0][ar1] = ra1.x; As[ak1+1][ar1] = ra1.y; As[ak1+2][ar1] = ra1.z; As[ak1+3][ar1] = ra1.w;
    *(float4*)&Bs[br0][bc0] = rb0;
    *(float4*)&Bs[br1][bc1] = rb1;
    __syncthreads();

    float acc[8][8];
    #pragma unroll
    for (int i = 0; i < 8; ++i)
        #pragma unroll
        for (int j = 0; j < 8; ++j) acc[i][j] = 0.f;

    const int nt = K / BK;
    for (int t = 0; t < nt; ++t) {
        if (t + 1 < nt) {
            const int kt = (t + 1) * BK;
            ra0 = *(const float4*)&A[(m0 + ar0) * K + kt + ak0];
            ra1 = *(const float4*)&A[(m0 + ar1) * K + kt + ak1];
            rb0 = *(const float4*)&Bm[(kt + br0) * N + n0 + bc0];
            rb1 = *(const float4*)&Bm[(kt + br1) * N + n0 + bc1];
        }
        #pragma unroll
        for (int kk = 0; kk < BK; ++kk) {
            float4 a0 = *(float4*)&As[kk][ty * 4];
            float4 a1 = *(float4*)&As[kk][64 + ty * 4];
            float4 b0 = *(float4*)&Bs[kk][tx * 4];
            float4 b1 = *(float4*)&Bs[kk][64 + tx * 4];
            float av[8] = {a0.x, a0.y, a0.z, a0.w, a1.x, a1.y, a1.z, a1.w};
            float bv[8] = {b0.x, b0.y, b0.z, b0.w, b1.x, b1.y, b1.z, b1.w};
            #pragma unroll
            for (int i = 0; i < 8; ++i)
                #pragma unroll
                for (int j = 0; j < 8; ++j)
                    acc[i][j] = fmaf(av[i], bv[j], acc[i][j]);
        }
        __syncthreads();
        if (t + 1 < nt) {
            As[ak0+0][ar0] = ra0.x; As[ak0+1][ar0] = ra0.y; As[ak0+2][ar0] = ra0.z; As[ak0+3][ar0] = ra0.w;
            As[ak1+0][ar1] = ra1.x; As[ak1+1][ar1] = ra1.y; As[ak1+2][ar1] = ra1.z; As[ak1+3][ar1] = ra1.w;
            *(float4*)&Bs[br0][bc0] = rb0;
            *(float4*)&Bs[br1][bc1] = rb1;
            __syncthreads();
        }
    }

    // epilogue: acc + bias
    #pragma unroll
    for (int i = 0; i < 8; ++i) {
        const int row = (i < 4) ? (ty * 4 + i) : (64 + ty * 4 + (i - 4));
        const int gr = (m0 + row) * N + n0;
        float4 c0, c1;
        c0.x = acc[i][0] + __ldg(&bias[n0 + tx*4 + 0]);
        c0.y = acc[i][1] + __ldg(&bias[n0 + tx*4 + 1]);
        c0.z = acc[i][2] + __ldg(&bias[n0 + tx*4 + 2]);
        c0.w = acc[i][3] + __ldg(&bias[n0 + tx*4 + 3]);
        c1.x = acc[i][4] + __ldg(&bias[n0 + 64 + tx*4 + 0]);
        c1.y = acc[i][5] + __ldg(&bias[n0 + 64 + tx*4 + 1]);
        c1.z = acc[i][6] + __ldg(&bias[n0 + 64 + tx*4 + 2]);
        c1.w = acc[i][7] + __ldg(&bias[n0 + 64 + tx*4 + 3]);
        *(float4*)&C[gr + tx * 4]      = c0;
        *(float4*)&C[gr + 64 + tx * 4] = c1;
    }
}

// =================================================================
// Flash attention, fp32, causal.
// Block = one (b, h, q-tile of 64 rows). 256 threads; thread (tx,ty)
// owns q-rows ty*4..+3 and 4 columns (kv cols / hd cols) tx*4..+3.
// smem (stride 68 for conflict-free LDS.128):
//   sQ: [hd][qrow]  (transposed, pre-scaled by 1/sqrt(hd))
//   sK: [hd][kvrow] (transposed)
//   sV: [kv][hd]    (natural)
//   sP: [kv][qrow]  (transposed)
// =================================================================
#define ASP 68
#define ATT_SMEM (4 * 64 * ASP * sizeof(float))

__global__ __launch_bounds__(256) void attn_kernel(
    const float* __restrict__ qkv, float* __restrict__ y)
{
    extern __shared__ float sm[];
    float* sQ = sm;
    float* sK = sQ + 64 * ASP;
    float* sV = sK + 64 * ASP;
    float* sP = sV + 64 * ASP;

    const int tid = threadIdx.x;
    const int tx = tid & 15, ty = tid >> 4;
    const int tm = ty * 4, tn = tx * 4;
    const int qt = blockIdx.x;            // q tile (0..31)
    const int bh = blockIdx.y;            // b*16 + h
    const int b = bh >> 4, h = bh & 15;
    const int qbase = qt * 64;
    const int rowbase = b * SEQ;          // token row offset

    // load Q (transposed + scaled)
    const float scale = 0.125f;           // 1/sqrt(64)
    for (int u = tid; u < 1024; u += 256) {
        const int row = u >> 4, c4 = (u & 15) << 2;
        float4 qv = *(const float4*)&qkv[(rowbase + qbase + row) * C3 + h * HDIM + c4];
        sQ[(c4+0)*ASP + row] = qv.x * scale;
        sQ[(c4+1)*ASP + row] = qv.y * scale;
        sQ[(c4+2)*ASP + row] = qv.z * scale;
        sQ[(c4+3)*ASP + row] = qv.w * scale;
    }

    float o[4][4];
    float mrow[4], lrow[4];
    #pragma unroll
    for (int i = 0; i < 4; ++i) {
        mrow[i] = -1e30f; lrow[i] = 0.f;
        #pragma unroll
        for (int j = 0; j < 4; ++j) o[i][j] = 0.f;
    }

    for (int jt = 0; jt <= qt; ++jt) {
        const int jb = jt * 64;
        __syncthreads();  // previous iter done with sK/sV/sP (also orders sQ on jt=0)

        // load K (transposed) + V (natural)
        for (int u = tid; u < 1024; u += 256) {
            const int row = u >> 4, c4 = (u & 15) << 2;
            const float* kp = &qkv[(rowbase + jb + row) * C3 + CDIM + h * HDIM + c4];
            float4 kv4 = *(const float4*)kp;
            sK[(c4+0)*ASP + row] = kv4.x;
            sK[(c4+1)*ASP + row] = kv4.y;
            sK[(c4+2)*ASP + row] = kv4.z;
            sK[(c4+3)*ASP + row] = kv4.w;
            float4 vv4 = *(const float4*)(kp + CDIM);  // V is +1024 cols from K
            *(float4*)&sV[row * ASP + c4] = vv4;
        }
        __syncthreads();

        // S = (Q*scale) @ K^T   (4x4 per thread)
        float s[4][4];
        #pragma unroll
        for (int i = 0; i < 4; ++i)
            #pragma unroll
            for (int j = 0; j < 4; ++j) s[i][j] = 0.f;

        #pragma unroll 16
        for (int kk = 0; kk < 64; ++kk) {
            float4 qa = *(float4*)&sQ[kk * ASP + tm];
            float4 ka = *(float4*)&sK[kk * ASP + tn];
            float qv[4] = {qa.x, qa.y, qa.z, qa.w};
            float kv[4] = {ka.x, ka.y, ka.z, ka.w};
            #pragma unroll
            for (int i = 0; i < 4; ++i)
                #pragma unroll
                for (int j = 0; j < 4; ++j)
                    s[i][j] = fmaf(qv[i], kv[j], s[i][j]);
        }

        // causal mask (only diagonal tile can be partially masked)
        if (jt == qt) {
            #pragma unroll
            for (int i = 0; i < 4; ++i)
                #pragma unroll
                for (int j = 0; j < 4; ++j)
                    if (jb + tn + j > qbase + tm + i) s[i][j] = -1e30f;
        }

        // online softmax update (row reductions across the 16 tx lanes)
        #pragma unroll
        for (int i = 0; i < 4; ++i) {
            float mx = fmaxf(fmaxf(s[i][0], s[i][1]), fmaxf(s[i][2], s[i][3]));
            #pragma unroll
            for (int off = 1; off < 16; off <<= 1)
                mx = fmaxf(mx, __shfl_xor_sync(0xffffffffu, mx, off));
            const float mnew = fmaxf(mrow[i], mx);
            const float corr = __expf(mrow[i] - mnew);
            float rs = 0.f;
            #pragma unroll
            for (int j = 0; j < 4; ++j) {
                s[i][j] = __expf(s[i][j] - mnew);
                rs += s[i][j];
            }
            #pragma unroll
            for (int off = 1; off < 16; off <<= 1)
                rs += __shfl_xor_sync(0xffffffffu, rs, off);
            lrow[i] = lrow[i] * corr + rs;
            mrow[i] = mnew;
            #pragma unroll
            for (int j = 0; j < 4; ++j) o[i][j] *= corr;
        }

        // store P transposed: sP[kvcol][qrow]
        #pragma unroll
        for (int j = 0; j < 4; ++j) {
            float4 pc = make_float4(s[0][j], s[1][j], s[2][j], s[3][j]);
            *(float4*)&sP[(tn + j) * ASP + tm] = pc;
        }
        __syncthreads();

        // O += P @ V
        #pragma unroll 16
        for (int kvk = 0; kvk < 64; ++kvk) {
            float4 pa = *(float4*)&sP[kvk * ASP + tm];
            float4 va = *(float4*)&sV[kvk * ASP + tn];
            float pv[4] = {pa.x, pa.y, pa.z, pa.w};
            float vv[4] = {va.x, va.y, va.z, va.w};
            #pragma unroll
            for (int i = 0; i < 4; ++i)
                #pragma unroll
                for (int j = 0; j < 4; ++j)
                    o[i][j] = fmaf(pv[i], vv[j], o[i][j]);
        }
    }

    // finalize: divide by l, write y[(b*T+t)*C + h*64 + d]
    #pragma unroll
    for (int i = 0; i < 4; ++i) {
        const float inv = 1.f / lrow[i];
        float4 ov = make_float4(o[i][0]*inv, o[i][1]*inv, o[i][2]*inv, o[i][3]*inv);
        *(float4*)&y[(rowbase + qbase + tm + i) * CDIM + h * HDIM + tn] = ov;
    }
}

// =================================================================
// launch
// =================================================================
extern "C" void kernel_launch(void* const* d_in, const int* in_sizes, int n_in,
                              void* d_out, int out_size)
{
    const float* x      = (const float*)d_in[0];
    const float* w_attn = (const float*)d_in[1];
    const float* b_attn = (const float*)d_in[2];
    const float* w_proj = (const float*)d_in[3];
    const float* b_proj = (const float*)d_in[4];
    float* out = (float*)d_out;

    float *qkv, *y;
    cudaGetSymbolAddress((void**)&qkv, g_qkv);
    cudaGetSymbolAddress((void**)&y, g_y);

    // qkv = x @ w_attn + b_attn : [8192,1024]@[1024,3072]
    sgemm_bias_kernel<<<dim3(C3 / BN, MROWS / BM), 256>>>(
        x, w_attn, b_attn, qkv, MROWS, C3, CDIM);

    // flash attention
    cudaFuncSetAttribute(attn_kernel, cudaFuncAttributeMaxDynamicSharedMemorySize,
                         (int)ATT_SMEM);
    attn_kernel<<<dim3(SEQ / 64, BATCH * NHEAD), 256, ATT_SMEM>>>(qkv, y);

    // out = y @ w_proj + b_proj : [8192,1024]@[1024,1024]
    sgemm_bias_kernel<<<dim3(CDIM / BN, MROWS / BM), 256>>>(
        y, w_proj, b_proj, out, MROWS, CDIM, CDIM);
}

// round 6
// speedup vs baseline: 1.5295x; 1.5295x over previous
#include <cuda_runtime.h>
#include <cuda_bf16.h>
#include <cstdint>

// ---------------- problem constants ----------------
#define BATCH 4
#define SEQ   2048
#define CDIM  1024
#define NHEAD 16
#define HDIM  64
#define C3    (3*CDIM)
#define MROWS (BATCH*SEQ)   // 8192

// ---------------- scratch (device globals: allocation-free) ----------------
__device__ float g_qkv[MROWS * C3];        // [8192, 3072]
__device__ float g_y[MROWS * CDIM];        // [8192, 1024]  (rna-rounded by attention)
__device__ float g_xr[MROWS * CDIM];       // rna-rounded x
__device__ float g_waT[C3 * CDIM];         // w_attn^T [3072,1024], rna-rounded
__device__ float g_wpT[CDIM * CDIM];       // w_proj^T [1024,1024], rna-rounded

// ---------------- helpers ----------------
__device__ __forceinline__ float rna_tf32(float v) {
    uint32_t u;
    asm("cvt.rna.tf32.f32 %0, %1;" : "=r"(u) : "f"(v));
    return __uint_as_float(u);
}

__device__ __forceinline__ uint32_t smem_u32(const void* p) {
    uint32_t a;
    asm("{ .reg .u64 t; cvta.to.shared.u64 t, %1; cvt.u32.u64 %0, t; }" : "=r"(a) : "l"(p));
    return a;
}

__device__ __forceinline__ void cp_async16(uint32_t s, const void* g) {
    asm volatile("cp.async.cg.shared.global [%0], [%1], 16;" :: "r"(s), "l"(g));
}

__device__ __forceinline__ void ldsm_x4(uint32_t addr, uint32_t& r0, uint32_t& r1,
                                        uint32_t& r2, uint32_t& r3) {
    asm volatile("ldmatrix.sync.aligned.m8n8.x4.shared.b16 {%0,%1,%2,%3}, [%4];"
                 : "=r"(r0), "=r"(r1), "=r"(r2), "=r"(r3) : "r"(addr));
}

__device__ __forceinline__ void mma_tf32(float& c0, float& c1, float& c2, float& c3,
                                         uint32_t a0, uint32_t a1, uint32_t a2, uint32_t a3,
                                         uint32_t b0, uint32_t b1) {
    asm volatile(
        "mma.sync.aligned.m16n8k8.row.col.f32.tf32.tf32.f32 "
        "{%0,%1,%2,%3}, {%4,%5,%6,%7}, {%8,%9}, {%0,%1,%2,%3};"
        : "+f"(c0), "+f"(c1), "+f"(c2), "+f"(c3)
        : "r"(a0), "r"(a1), "r"(a2), "r"(a3), "r"(b0), "r"(b1));
}

// =================================================================
// tf32 mma.sync GEMM: C[M,N] = A[M,K] @ Bt[N,K]^T + bias[N]
// CTA tile 128x128, BK=32, 256 threads (8 warps, 2x4 warp grid,
// warp tile 64x32). 3-stage cp.async pipeline. Smem rows padded to
// 36 floats (144B) so ldmatrix.x4 (8 rows x 16B) is conflict-free.
// =================================================================
#define BM 128
#define BN 128
#define BK 32
#define APAD 36
#define TILE_BYTES (128 * APAD * 4)          // 18432 per operand tile
#define STAGE_BYTES (2 * TILE_BYTES)         // 36864
#define NSTAGE 3
#define GEMM_SMEM (NSTAGE * STAGE_BYTES)     // 110592

__global__ __launch_bounds__(256, 1) void tf32_gemm_kernel(
    const float* __restrict__ A, const float* __restrict__ Bt,
    const float* __restrict__ bias, float* __restrict__ C,
    int M, int N, int K)
{
    extern __shared__ __align__(128) char smem_raw[];
    const uint32_t sbase = smem_u32(smem_raw);

    const int tid = threadIdx.x;
    const int wid = tid >> 5, lane = tid & 31;
    const int warp_m = wid >> 2;         // 0..1 -> 64-row half
    const int warp_n = wid & 3;          // 0..3 -> 32-col slice
    const int m0 = blockIdx.y * BM;
    const int n0 = blockIdx.x * BN;

    // ---- per-thread cp.async chunk mapping (4 chunks per operand tile) ----
    // chunk u: row = u>>3 (0..127), cc = u&7 (16B column chunk)
    uint32_t s_off[4];
    const float* gA[4];
    const float* gB[4];
    #pragma unroll
    for (int i = 0; i < 4; ++i) {
        const int u = tid + 256 * i;
        const int row = u >> 3, cc = u & 7;
        s_off[i] = (uint32_t)(row * APAD + cc * 4) * 4;
        gA[i] = A  + (size_t)(m0 + row) * K + cc * 4;
        gB[i] = Bt + (size_t)(n0 + row) * K + cc * 4;
    }

    // ---- per-lane ldmatrix base offsets (bytes within a stage) ----
    // A fragment for m16 block i: matrices (rows0-7,k0-3)(rows8-15,k0-3)(rows0-7,k4-7)(rows8-15,k4-7)
    uint32_t a_off[4];
    {
        const int r = (lane & 7) + ((lane >> 3) & 1) * 8;   // row within m16
        const int cg = (lane >> 4) * 4;                     // k group 0 or 4
        #pragma unroll
        for (int i = 0; i < 4; ++i)
            a_off[i] = (uint32_t)((warp_m * 64 + 16 * i + r) * APAD + cg) * 4;
    }
    // B fragment pair p covers n8 blocks {2p, 2p+1}:
    // matrices (n0-7,k0-3)(n0-7,k4-7)(n8-15,k0-3)(n8-15,k4-7)
    uint32_t b_off[2];
    {
        const int r = (lane & 7) + ((lane >> 4) & 1) * 8;
        const int cg = ((lane >> 3) & 1) * 4;
        #pragma unroll
        for (int p = 0; p < 2; ++p)
            b_off[p] = (uint32_t)(TILE_BYTES) +
                       (uint32_t)((warp_n * 32 + 16 * p + r) * APAD + cg) * 4;
    }

    float acc[4][4][4];
    #pragma unroll
    for (int i = 0; i < 4; ++i)
        #pragma unroll
        for (int j = 0; j < 4; ++j)
            #pragma unroll
            for (int q = 0; q < 4; ++q) acc[i][j][q] = 0.f;

    const int NT = K / BK;

    // ---- prologue: issue 2 stages ----
    #pragma unroll
    for (int t = 0; t < 2; ++t) {
        const uint32_t sb = sbase + t * STAGE_BYTES;
        #pragma unroll
        for (int i = 0; i < 4; ++i) cp_async16(sb + s_off[i], gA[i] + t * BK);
        #pragma unroll
        for (int i = 0; i < 4; ++i) cp_async16(sb + TILE_BYTES + s_off[i], gB[i] + t * BK);
        asm volatile("cp.async.commit_group;");
    }

    for (int t = 0; t < NT; ++t) {
        asm volatile("cp.async.wait_group 1;");
        __syncthreads();

        // issue loads for t+2
        if (t + 2 < NT) {
            const int sp = (t + 2) % NSTAGE;
            const uint32_t sb = sbase + sp * STAGE_BYTES;
            #pragma unroll
            for (int i = 0; i < 4; ++i) cp_async16(sb + s_off[i], gA[i] + (t + 2) * BK);
            #pragma unroll
            for (int i = 0; i < 4; ++i) cp_async16(sb + TILE_BYTES + s_off[i], gB[i] + (t + 2) * BK);
        }
        asm volatile("cp.async.commit_group;");

        // compute on stage t%3
        const uint32_t st = sbase + (t % NSTAGE) * STAGE_BYTES;
        #pragma unroll
        for (int ks = 0; ks < 4; ++ks) {
            const uint32_t ko = (uint32_t)(ks * 8 * 4);   // 8 floats per k-step
            uint32_t af[4][4], bf[4][2];
            #pragma unroll
            for (int i = 0; i < 4; ++i)
                ldsm_x4(st + a_off[i] + ko, af[i][0], af[i][1], af[i][2], af[i][3]);
            #pragma unroll
            for (int p = 0; p < 2; ++p)
                ldsm_x4(st + b_off[p] + ko,
                        bf[2*p][0], bf[2*p][1], bf[2*p+1][0], bf[2*p+1][1]);
            #pragma unroll
            for (int i = 0; i < 4; ++i)
                #pragma unroll
                for (int j = 0; j < 4; ++j)
                    mma_tf32(acc[i][j][0], acc[i][j][1], acc[i][j][2], acc[i][j][3],
                             af[i][0], af[i][1], af[i][2], af[i][3],
                             bf[j][0], bf[j][1]);
        }
    }

    // ---- epilogue: bias + store ----
    const int g = lane >> 2, c = lane & 3;
    #pragma unroll
    for (int i = 0; i < 4; ++i) {
        const int row_a = m0 + warp_m * 64 + 16 * i + g;
        #pragma unroll
        for (int j = 0; j < 4; ++j) {
            const int col = n0 + warp_n * 32 + 8 * j + 2 * c;
            const float b0 = bias[col], b1 = bias[col + 1];
            float2 v0 = make_float2(acc[i][j][0] + b0, acc[i][j][1] + b1);
            float2 v1 = make_float2(acc[i][j][2] + b0, acc[i][j][3] + b1);
            *(float2*)&C[(size_t)row_a * N + col]       = v0;
            *(float2*)&C[(size_t)(row_a + 8) * N + col] = v1;
        }
    }
}

// =================================================================
// pre-pass: elementwise rna round (float4)
// =================================================================
__global__ __launch_bounds__(256) void rna_round_kernel(
    const float4* __restrict__ in, float4* __restrict__ out, int n4)
{
    int i = blockIdx.x * 256 + threadIdx.x;
    if (i < n4) {
        float4 v = in[i];
        v.x = rna_tf32(v.x); v.y = rna_tf32(v.y);
        v.z = rna_tf32(v.z); v.w = rna_tf32(v.w);
        out[i] = v;
    }
}

// =================================================================
// pre-pass: transpose + rna round: in[K][N] -> out[N][K]
// =================================================================
__global__ __launch_bounds__(256) void transpose_rna_kernel(
    const float* __restrict__ in, float* __restrict__ out, int K, int N)
{
    __shared__ float tile[32][33];
    const int k0 = blockIdx.y * 32, n0 = blockIdx.x * 32;
    const int tx = threadIdx.x, ty = threadIdx.y;   // 32 x 8
    #pragma unroll
    for (int i = 0; i < 32; i += 8)
        tile[ty + i][tx] = in[(size_t)(k0 + ty + i) * N + n0 + tx];
    __syncthreads();
    #pragma unroll
    for (int i = 0; i < 32; i += 8)
        out[(size_t)(n0 + ty + i) * K + k0 + tx] = rna_tf32(tile[tx][ty + i]);
}

// =================================================================
// Flash attention, fp32, causal (proven R1 version; output rna-rounded)
// =================================================================
#define ASP 68
#define ATT_SMEM (4 * 64 * ASP * sizeof(float))

__global__ __launch_bounds__(256) void attn_kernel(
    const float* __restrict__ qkv, float* __restrict__ y)
{
    extern __shared__ float sm[];
    float* sQ = sm;
    float* sK = sQ + 64 * ASP;
    float* sV = sK + 64 * ASP;
    float* sP = sV + 64 * ASP;

    const int tid = threadIdx.x;
    const int tx = tid & 15, ty = tid >> 4;
    const int tm = ty * 4, tn = tx * 4;
    const int qt = blockIdx.x;
    const int bh = blockIdx.y;
    const int b = bh >> 4, h = bh & 15;
    const int qbase = qt * 64;
    const int rowbase = b * SEQ;

    const float scale = 0.125f;
    for (int u = tid; u < 1024; u += 256) {
        const int row = u >> 4, c4 = (u & 15) << 2;
        float4 qv = *(const float4*)&qkv[(size_t)(rowbase + qbase + row) * C3 + h * HDIM + c4];
        sQ[(c4+0)*ASP + row] = qv.x * scale;
        sQ[(c4+1)*ASP + row] = qv.y * scale;
        sQ[(c4+2)*ASP + row] = qv.z * scale;
        sQ[(c4+3)*ASP + row] = qv.w * scale;
    }

    float o[4][4];
    float mrow[4], lrow[4];
    #pragma unroll
    for (int i = 0; i < 4; ++i) {
        mrow[i] = -1e30f; lrow[i] = 0.f;
        #pragma unroll
        for (int j = 0; j < 4; ++j) o[i][j] = 0.f;
    }

    for (int jt = 0; jt <= qt; ++jt) {
        const int jb = jt * 64;
        __syncthreads();

        for (int u = tid; u < 1024; u += 256) {
            const int row = u >> 4, c4 = (u & 15) << 2;
            const float* kp = &qkv[(size_t)(rowbase + jb + row) * C3 + CDIM + h * HDIM + c4];
            float4 kv4 = *(const float4*)kp;
            sK[(c4+0)*ASP + row] = kv4.x;
            sK[(c4+1)*ASP + row] = kv4.y;
            sK[(c4+2)*ASP + row] = kv4.z;
            sK[(c4+3)*ASP + row] = kv4.w;
            float4 vv4 = *(const float4*)(kp + CDIM);
            *(float4*)&sV[row * ASP + c4] = vv4;
        }
        __syncthreads();

        float s[4][4];
        #pragma unroll
        for (int i = 0; i < 4; ++i)
            #pragma unroll
            for (int j = 0; j < 4; ++j) s[i][j] = 0.f;

        #pragma unroll 16
        for (int kk = 0; kk < 64; ++kk) {
            float4 qa = *(float4*)&sQ[kk * ASP + tm];
            float4 ka = *(float4*)&sK[kk * ASP + tn];
            float qv[4] = {qa.x, qa.y, qa.z, qa.w};
            float kv[4] = {ka.x, ka.y, ka.z, ka.w};
            #pragma unroll
            for (int i = 0; i < 4; ++i)
                #pragma unroll
                for (int j = 0; j < 4; ++j)
                    s[i][j] = fmaf(qv[i], kv[j], s[i][j]);
        }

        if (jt == qt) {
            #pragma unroll
            for (int i = 0; i < 4; ++i)
                #pragma unroll
                for (int j = 0; j < 4; ++j)
                    if (jb + tn + j > qbase + tm + i) s[i][j] = -1e30f;
        }

        #pragma unroll
        for (int i = 0; i < 4; ++i) {
            float mx = fmaxf(fmaxf(s[i][0], s[i][1]), fmaxf(s[i][2], s[i][3]));
            #pragma unroll
            for (int off = 1; off < 16; off <<= 1)
                mx = fmaxf(mx, __shfl_xor_sync(0xffffffffu, mx, off));
            const float mnew = fmaxf(mrow[i], mx);
            const float corr = __expf(mrow[i] - mnew);
            float rs = 0.f;
            #pragma unroll
            for (int j = 0; j < 4; ++j) {
                s[i][j] = __expf(s[i][j] - mnew);
                rs += s[i][j];
            }
            #pragma unroll
            for (int off = 1; off < 16; off <<= 1)
                rs += __shfl_xor_sync(0xffffffffu, rs, off);
            lrow[i] = lrow[i] * corr + rs;
            mrow[i] = mnew;
            #pragma unroll
            for (int j = 0; j < 4; ++j) o[i][j] *= corr;
        }

        #pragma unroll
        for (int j = 0; j < 4; ++j) {
            float4 pc = make_float4(s[0][j], s[1][j], s[2][j], s[3][j]);
            *(float4*)&sP[(tn + j) * ASP + tm] = pc;
        }
        __syncthreads();

        #pragma unroll 16
        for (int kvk = 0; kvk < 64; ++kvk) {
            float4 pa = *(float4*)&sP[kvk * ASP + tm];
            float4 va = *(float4*)&sV[kvk * ASP + tn];
            float pv[4] = {pa.x, pa.y, pa.z, pa.w};
            float vv[4] = {va.x, va.y, va.z, va.w};
            #pragma unroll
            for (int i = 0; i < 4; ++i)
                #pragma unroll
                for (int j = 0; j < 4; ++j)
                    o[i][j] = fmaf(pv[i], vv[j], o[i][j]);
        }
    }

    #pragma unroll
    for (int i = 0; i < 4; ++i) {
        const float inv = 1.f / lrow[i];
        float4 ov = make_float4(rna_tf32(o[i][0]*inv), rna_tf32(o[i][1]*inv),
                                rna_tf32(o[i][2]*inv), rna_tf32(o[i][3]*inv));
        *(float4*)&y[(size_t)(rowbase + qbase + tm + i) * CDIM + h * HDIM + tn] = ov;
    }
}

// =================================================================
// launch
// =================================================================
extern "C" void kernel_launch(void* const* d_in, const int* in_sizes, int n_in,
                              void* d_out, int out_size)
{
    const float* x      = (const float*)d_in[0];
    const float* w_attn = (const float*)d_in[1];
    const float* b_attn = (const float*)d_in[2];
    const float* w_proj = (const float*)d_in[3];
    const float* b_proj = (const float*)d_in[4];
    float* out = (float*)d_out;

    float *qkv, *y, *xr, *waT, *wpT;
    cudaGetSymbolAddress((void**)&qkv, g_qkv);
    cudaGetSymbolAddress((void**)&y,   g_y);
    cudaGetSymbolAddress((void**)&xr,  g_xr);
    cudaGetSymbolAddress((void**)&waT, g_waT);
    cudaGetSymbolAddress((void**)&wpT, g_wpT);

    cudaFuncSetAttribute(tf32_gemm_kernel,
                         cudaFuncAttributeMaxDynamicSharedMemorySize, GEMM_SMEM);
    cudaFuncSetAttribute(attn_kernel,
                         cudaFuncAttributeMaxDynamicSharedMemorySize, (int)ATT_SMEM);

    // 1. round x -> xr
    {
        int n4 = MROWS * CDIM / 4;
        rna_round_kernel<<<(n4 + 255) / 256, 256>>>((const float4*)x, (float4*)xr, n4);
    }
    // 2. transpose+round weights
    transpose_rna_kernel<<<dim3(C3 / 32, CDIM / 32), dim3(32, 8)>>>(w_attn, waT, CDIM, C3);
    transpose_rna_kernel<<<dim3(CDIM / 32, CDIM / 32), dim3(32, 8)>>>(w_proj, wpT, CDIM, CDIM);

    // 3. qkv = xr @ waT^T + b_attn
    tf32_gemm_kernel<<<dim3(C3 / BN, MROWS / BM), 256, GEMM_SMEM>>>(
        xr, waT, b_attn, qkv, MROWS, C3, CDIM);

    // 4. flash attention (writes rna-rounded y)
    attn_kernel<<<dim3(SEQ / 64, BATCH * NHEAD), 256, ATT_SMEM>>>(qkv, y);

    // 5. out = y @ wpT^T + b_proj
    tf32_gemm_kernel<<<dim3(CDIM / BN, MROWS / BM), 256, GEMM_SMEM>>>(
        y, wpT, b_proj, out, MROWS, CDIM, CDIM);
}

// round 10
// speedup vs baseline: 2.6644x; 1.7421x over previous
#include <cuda_runtime.h>
#include <cuda_bf16.h>
#include <cstdint>

// ---------------- problem constants ----------------
#define BATCH 4
#define SEQ   2048
#define CDIM  1024
#define NHEAD 16
#define HDIM  64
#define C3    (3*CDIM)
#define MROWS (BATCH*SEQ)   // 8192

// ---------------- scratch (device globals: allocation-free) ----------------
__device__ float g_qkv[MROWS * C3];        // [8192, 3072]
__device__ float g_y[MROWS * CDIM];        // [8192, 1024]  (rna-rounded by attention)
__device__ float g_xr[MROWS * CDIM];       // rna-rounded x
__device__ float g_waT[C3 * CDIM];         // w_attn^T [3072,1024], rna-rounded
__device__ float g_wpT[CDIM * CDIM];       // w_proj^T [1024,1024], rna-rounded

// ---------------- helpers ----------------
__device__ __forceinline__ float rna_tf32(float v) {
    uint32_t u;
    asm("cvt.rna.tf32.f32 %0, %1;" : "=r"(u) : "f"(v));
    return __uint_as_float(u);
}

__device__ __forceinline__ uint32_t smem_u32(const void* p) {
    uint32_t a;
    asm("{ .reg .u64 t; cvta.to.shared.u64 t, %1; cvt.u32.u64 %0, t; }" : "=r"(a) : "l"(p));
    return a;
}

__device__ __forceinline__ void cp_async16(uint32_t s, const void* g) {
    asm volatile("cp.async.cg.shared.global [%0], [%1], 16;" :: "r"(s), "l"(g));
}

__device__ __forceinline__ void ldsm_x4(uint32_t addr, uint32_t& r0, uint32_t& r1,
                                        uint32_t& r2, uint32_t& r3) {
    asm volatile("ldmatrix.sync.aligned.m8n8.x4.shared.b16 {%0,%1,%2,%3}, [%4];"
                 : "=r"(r0), "=r"(r1), "=r"(r2), "=r"(r3) : "r"(addr));
}

__device__ __forceinline__ void mma_tf32(float& c0, float& c1, float& c2, float& c3,
                                         uint32_t a0, uint32_t a1, uint32_t a2, uint32_t a3,
                                         uint32_t b0, uint32_t b1) {
    asm volatile(
        "mma.sync.aligned.m16n8k8.row.col.f32.tf32.tf32.f32 "
        "{%0,%1,%2,%3}, {%4,%5,%6,%7}, {%8,%9}, {%0,%1,%2,%3};"
        : "+f"(c0), "+f"(c1), "+f"(c2), "+f"(c3)
        : "r"(a0), "r"(a1), "r"(a2), "r"(a3), "r"(b0), "r"(b1));
}

// =================================================================
// tf32 mma.sync GEMM: C[M,N] = A[M,K] @ Bt[N,K]^T + bias[N]
// (unchanged from R6 — validated)
// =================================================================
#define BM 128
#define BN 128
#define BK 32
#define APAD 36
#define TILE_BYTES (128 * APAD * 4)
#define STAGE_BYTES (2 * TILE_BYTES)
#define NSTAGE 3
#define GEMM_SMEM (NSTAGE * STAGE_BYTES)

__global__ __launch_bounds__(256, 1) void tf32_gemm_kernel(
    const float* __restrict__ A, const float* __restrict__ Bt,
    const float* __restrict__ bias, float* __restrict__ C,
    int M, int N, int K)
{
    extern __shared__ __align__(128) char smem_raw[];
    const uint32_t sbase = smem_u32(smem_raw);

    const int tid = threadIdx.x;
    const int wid = tid >> 5, lane = tid & 31;
    const int warp_m = wid >> 2;
    const int warp_n = wid & 3;
    const int m0 = blockIdx.y * BM;
    const int n0 = blockIdx.x * BN;

    uint32_t s_off[4];
    const float* gA[4];
    const float* gB[4];
    #pragma unroll
    for (int i = 0; i < 4; ++i) {
        const int u = tid + 256 * i;
        const int row = u >> 3, cc = u & 7;
        s_off[i] = (uint32_t)(row * APAD + cc * 4) * 4;
        gA[i] = A  + (size_t)(m0 + row) * K + cc * 4;
        gB[i] = Bt + (size_t)(n0 + row) * K + cc * 4;
    }

    uint32_t a_off[4];
    {
        const int r = (lane & 7) + ((lane >> 3) & 1) * 8;
        const int cg = (lane >> 4) * 4;
        #pragma unroll
        for (int i = 0; i < 4; ++i)
            a_off[i] = (uint32_t)((warp_m * 64 + 16 * i + r) * APAD + cg) * 4;
    }
    uint32_t b_off[2];
    {
        const int r = (lane & 7) + ((lane >> 4) & 1) * 8;
        const int cg = ((lane >> 3) & 1) * 4;
        #pragma unroll
        for (int p = 0; p < 2; ++p)
            b_off[p] = (uint32_t)(TILE_BYTES) +
                       (uint32_t)((warp_n * 32 + 16 * p + r) * APAD + cg) * 4;
    }

    float acc[4][4][4];
    #pragma unroll
    for (int i = 0; i < 4; ++i)
        #pragma unroll
        for (int j = 0; j < 4; ++j)
            #pragma unroll
            for (int q = 0; q < 4; ++q) acc[i][j][q] = 0.f;

    const int NT = K / BK;

    #pragma unroll
    for (int t = 0; t < 2; ++t) {
        const uint32_t sb = sbase + t * STAGE_BYTES;
        #pragma unroll
        for (int i = 0; i < 4; ++i) cp_async16(sb + s_off[i], gA[i] + t * BK);
        #pragma unroll
        for (int i = 0; i < 4; ++i) cp_async16(sb + TILE_BYTES + s_off[i], gB[i] + t * BK);
        asm volatile("cp.async.commit_group;");
    }

    for (int t = 0; t < NT; ++t) {
        asm volatile("cp.async.wait_group 1;");
        __syncthreads();

        if (t + 2 < NT) {
            const int sp = (t + 2) % NSTAGE;
            const uint32_t sb = sbase + sp * STAGE_BYTES;
            #pragma unroll
            for (int i = 0; i < 4; ++i) cp_async16(sb + s_off[i], gA[i] + (t + 2) * BK);
            #pragma unroll
            for (int i = 0; i < 4; ++i) cp_async16(sb + TILE_BYTES + s_off[i], gB[i] + (t + 2) * BK);
        }
        asm volatile("cp.async.commit_group;");

        const uint32_t st = sbase + (t % NSTAGE) * STAGE_BYTES;
        #pragma unroll
        for (int ks = 0; ks < 4; ++ks) {
            const uint32_t ko = (uint32_t)(ks * 8 * 4);
            uint32_t af[4][4], bf[4][2];
            #pragma unroll
            for (int i = 0; i < 4; ++i)
                ldsm_x4(st + a_off[i] + ko, af[i][0], af[i][1], af[i][2], af[i][3]);
            #pragma unroll
            for (int p = 0; p < 2; ++p)
                ldsm_x4(st + b_off[p] + ko,
                        bf[2*p][0], bf[2*p][1], bf[2*p+1][0], bf[2*p+1][1]);
            #pragma unroll
            for (int i = 0; i < 4; ++i)
                #pragma unroll
                for (int j = 0; j < 4; ++j)
                    mma_tf32(acc[i][j][0], acc[i][j][1], acc[i][j][2], acc[i][j][3],
                             af[i][0], af[i][1], af[i][2], af[i][3],
                             bf[j][0], bf[j][1]);
        }
    }

    const int g = lane >> 2, c = lane & 3;
    #pragma unroll
    for (int i = 0; i < 4; ++i) {
        const int row_a = m0 + warp_m * 64 + 16 * i + g;
        #pragma unroll
        for (int j = 0; j < 4; ++j) {
            const int col = n0 + warp_n * 32 + 8 * j + 2 * c;
            const float b0 = bias[col], b1 = bias[col + 1];
            float2 v0 = make_float2(acc[i][j][0] + b0, acc[i][j][1] + b1);
            float2 v1 = make_float2(acc[i][j][2] + b0, acc[i][j][3] + b1);
            *(float2*)&C[(size_t)row_a * N + col]       = v0;
            *(float2*)&C[(size_t)(row_a + 8) * N + col] = v1;
        }
    }
}

// =================================================================
// pre-pass kernels (unchanged)
// =================================================================
__global__ __launch_bounds__(256) void rna_round_kernel(
    const float4* __restrict__ in, float4* __restrict__ out, int n4)
{
    int i = blockIdx.x * 256 + threadIdx.x;
    if (i < n4) {
        float4 v = in[i];
        v.x = rna_tf32(v.x); v.y = rna_tf32(v.y);
        v.z = rna_tf32(v.z); v.w = rna_tf32(v.w);
        out[i] = v;
    }
}

__global__ __launch_bounds__(256) void transpose_rna_kernel(
    const float* __restrict__ in, float* __restrict__ out, int K, int N)
{
    __shared__ float tile[32][33];
    const int k0 = blockIdx.y * 32, n0 = blockIdx.x * 32;
    const int tx = threadIdx.x, ty = threadIdx.y;
    #pragma unroll
    for (int i = 0; i < 32; i += 8)
        tile[ty + i][tx] = in[(size_t)(k0 + ty + i) * N + n0 + tx];
    __syncthreads();
    #pragma unroll
    for (int i = 0; i < 32; i += 8)
        out[(size_t)(n0 + ty + i) * K + k0 + tx] = rna_tf32(tile[tx][ty + i]);
}

// =================================================================
// Tensor-core flash attention (tf32 mma.sync), fp32 softmax, causal.
// Block: (b,h,64-row q tile), 128 threads / 4 warps; warp w owns q
// rows [16w,16w+16). smem arrays padded to 68 floats/row (272B ->
// 16B/row bank shift, conflict-free ldmatrix, same as GEMM's 36).
//   sQ [64 q ][68 hd]  A-operand of S      (pre-scaled, rna)
//   sK [64 kv][68 hd]  B-operand of S      (K-major, rna)
//   sVT[64 hd][68 kv]  B-operand of P@V    (V transposed, rna)
//   sP [64 q ][68 kv]  A-operand of P@V    (per-warp-disjoint rows)
// =================================================================
#define FPAD 68
#define ABYTES (64 * FPAD * 4)          // 17408
#define ATT_SMEM (4 * ABYTES)           // 69632

__global__ __launch_bounds__(128) void attn_mma_kernel(
    const float* __restrict__ qkv, float* __restrict__ y)
{
    extern __shared__ __align__(16) float sm[];
    float* sQ  = sm;
    float* sK  = sm + 64 * FPAD;
    float* sVT = sm + 2 * 64 * FPAD;
    float* sP  = sm + 3 * 64 * FPAD;

    const int tid = threadIdx.x;
    const int wid = tid >> 5, lane = tid & 31;
    const int qt = blockIdx.x;             // q tile 0..31
    const int bh = blockIdx.y;
    const int b = bh >> 4, h = bh & 15;
    const int qbase = qt * 64;
    const int rowbase = b * SEQ;

    const uint32_t sbase = smem_u32(sm);

    // ldmatrix per-lane offsets (identical mappings to the GEMM kernel)
    const int ar  = (lane & 7) + ((lane >> 3) & 1) * 8;
    const int acg = (lane >> 4) * 4;
    const uint32_t aoffQ = sbase + (uint32_t)((wid * 16 + ar) * FPAD + acg) * 4;
    const uint32_t aoffP = sbase + 3u * ABYTES + (uint32_t)((wid * 16 + ar) * FPAD + acg) * 4;

    const int br  = (lane & 7) + ((lane >> 4) & 1) * 8;
    const int bcg = ((lane >> 3) & 1) * 4;
    uint32_t boffK[4], boffV[4];
    #pragma unroll
    for (int p = 0; p < 4; ++p) {
        boffK[p] = sbase + 1u * ABYTES + (uint32_t)((16 * p + br) * FPAD + bcg) * 4;
        boffV[p] = sbase + 2u * ABYTES + (uint32_t)((16 * p + br) * FPAD + bcg) * 4;
    }

    // ---- load Q (scaled by 1/sqrt(hd), rna-rounded) ----
    for (int u = tid; u < 1024; u += 128) {
        const int row = u >> 4, c4 = (u & 15) << 2;
        float4 qv = *(const float4*)&qkv[(size_t)(rowbase + qbase + row) * C3 + h * HDIM + c4];
        float4 o;
        o.x = rna_tf32(qv.x * 0.125f); o.y = rna_tf32(qv.y * 0.125f);
        o.z = rna_tf32(qv.z * 0.125f); o.w = rna_tf32(qv.w * 0.125f);
        *(float4*)&sQ[row * FPAD + c4] = o;
    }

    // softmax state + output accumulators
    float m0 = -1e30f, m1 = -1e30f, l0 = 0.f, l1 = 0.f;
    float acc_o[8][4];
    #pragma unroll
    for (int j = 0; j < 8; ++j)
        #pragma unroll
        for (int q = 0; q < 4; ++q) acc_o[j][q] = 0.f;

    const int g = lane >> 2, c = lane & 3;

    for (int jt = 0; jt <= qt; ++jt) {
        __syncthreads();   // prev iter done with sK/sVT (and sQ visible on jt=0)

        // ---- load K (K-major) + V (transposed), rna-rounded ----
        for (int u = tid; u < 1024; u += 128) {
            const int row = u >> 4, c4 = (u & 15) << 2;
            const float* kp = &qkv[(size_t)(rowbase + jt * 64 + row) * C3 + CDIM + h * HDIM + c4];
            float4 kv4 = *(const float4*)kp;
            float4 ko;
            ko.x = rna_tf32(kv4.x); ko.y = rna_tf32(kv4.y);
            ko.z = rna_tf32(kv4.z); ko.w = rna_tf32(kv4.w);
            *(float4*)&sK[row * FPAD + c4] = ko;
            float4 vv4 = *(const float4*)(kp + CDIM);
            sVT[(c4 + 0) * FPAD + row] = rna_tf32(vv4.x);
            sVT[(c4 + 1) * FPAD + row] = rna_tf32(vv4.y);
            sVT[(c4 + 2) * FPAD + row] = rna_tf32(vv4.z);
            sVT[(c4 + 3) * FPAD + row] = rna_tf32(vv4.w);
        }
        __syncthreads();

        // ---- S = Q @ K^T ----
        float s[8][4];
        #pragma unroll
        for (int j = 0; j < 8; ++j)
            #pragma unroll
            for (int q = 0; q < 4; ++q) s[j][q] = 0.f;

        #pragma unroll
        for (int ks = 0; ks < 8; ++ks) {
            const uint32_t ko = (uint32_t)(ks * 32);
            uint32_t a0, a1, a2, a3;
            ldsm_x4(aoffQ + ko, a0, a1, a2, a3);
            uint32_t bf[8][2];
            #pragma unroll
            for (int p = 0; p < 4; ++p)
                ldsm_x4(boffK[p] + ko, bf[2*p][0], bf[2*p][1], bf[2*p+1][0], bf[2*p+1][1]);
            #pragma unroll
            for (int j = 0; j < 8; ++j)
                mma_tf32(s[j][0], s[j][1], s[j][2], s[j][3],
                         a0, a1, a2, a3, bf[j][0], bf[j][1]);
        }

        // ---- causal mask (diagonal tile only) ----
        if (jt == qt) {
            const int r0 = wid * 16 + g;       // relative q row
            const int r1 = r0 + 8;
            #pragma unroll
            for (int j = 0; j < 8; ++j) {
                const int col = 8 * j + 2 * c;
                if (col     > r0) s[j][0] = -1e30f;
                if (col + 1 > r0) s[j][1] = -1e30f;
                if (col     > r1) s[j][2] = -1e30f;
                if (col + 1 > r1) s[j][3] = -1e30f;
            }
        }

        // ---- online softmax (quad-lane row reduction) ----
        float mx0 = -1e30f, mx1 = -1e30f;
        #pragma unroll
        for (int j = 0; j < 8; ++j) {
            mx0 = fmaxf(mx0, fmaxf(s[j][0], s[j][1]));
            mx1 = fmaxf(mx1, fmaxf(s[j][2], s[j][3]));
        }
        mx0 = fmaxf(mx0, __shfl_xor_sync(0xffffffffu, mx0, 1));
        mx0 = fmaxf(mx0, __shfl_xor_sync(0xffffffffu, mx0, 2));
        mx1 = fmaxf(mx1, __shfl_xor_sync(0xffffffffu, mx1, 1));
        mx1 = fmaxf(mx1, __shfl_xor_sync(0xffffffffu, mx1, 2));

        const float mn0 = fmaxf(m0, mx0), mn1 = fmaxf(m1, mx1);
        const float corr0 = __expf(m0 - mn0), corr1 = __expf(m1 - mn1);
        float sum0 = 0.f, sum1 = 0.f;
        #pragma unroll
        for (int j = 0; j < 8; ++j) {
            s[j][0] = __expf(s[j][0] - mn0);
            s[j][1] = __expf(s[j][1] - mn0);
            s[j][2] = __expf(s[j][2] - mn1);
            s[j][3] = __expf(s[j][3] - mn1);
            sum0 += s[j][0] + s[j][1];
            sum1 += s[j][2] + s[j][3];
        }
        sum0 += __shfl_xor_sync(0xffffffffu, sum0, 1);
        sum0 += __shfl_xor_sync(0xffffffffu, sum0, 2);
        sum1 += __shfl_xor_sync(0xffffffffu, sum1, 1);
        sum1 += __shfl_xor_sync(0xffffffffu, sum1, 2);

        l0 = l0 * corr0 + sum0;  m0 = mn0;
        l1 = l1 * corr1 + sum1;  m1 = mn1;
        #pragma unroll
        for (int j = 0; j < 8; ++j) {
            acc_o[j][0] *= corr0; acc_o[j][1] *= corr0;
            acc_o[j][2] *= corr1; acc_o[j][3] *= corr1;
        }

        // ---- P -> smem (rna), per-warp-disjoint rows ----
        {
            float* p0 = &sP[(wid * 16 + g) * FPAD + 2 * c];
            float* p1 = &sP[(wid * 16 + 8 + g) * FPAD + 2 * c];
            #pragma unroll
            for (int j = 0; j < 8; ++j) {
                *(float2*)(p0 + 8 * j) = make_float2(rna_tf32(s[j][0]), rna_tf32(s[j][1]));
                *(float2*)(p1 + 8 * j) = make_float2(rna_tf32(s[j][2]), rna_tf32(s[j][3]));
            }
        }
        __syncwarp();

        // ---- O += P @ V  (A = sP, B = sVT, k = kv) ----
        #pragma unroll
        for (int ks = 0; ks < 8; ++ks) {
            const uint32_t ko = (uint32_t)(ks * 32);
            uint32_t a0, a1, a2, a3;
            ldsm_x4(aoffP + ko, a0, a1, a2, a3);
            uint32_t bf[8][2];
            #pragma unroll
            for (int p = 0; p < 4; ++p)
                ldsm_x4(boffV[p] + ko, bf[2*p][0], bf[2*p][1], bf[2*p+1][0], bf[2*p+1][1]);
            #pragma unroll
            for (int j = 0; j < 8; ++j)
                mma_tf32(acc_o[j][0], acc_o[j][1], acc_o[j][2], acc_o[j][3],
                         a0, a1, a2, a3, bf[j][0], bf[j][1]);
        }
    }

    // ---- finalize + store y (rna-rounded for the proj GEMM) ----
    const float inv0 = 1.f / l0, inv1 = 1.f / l1;
    const int grow0 = rowbase + qbase + wid * 16 + g;
    #pragma unroll
    for (int j = 0; j < 8; ++j) {
        const int col = h * HDIM + 8 * j + 2 * c;
        *(float2*)&y[(size_t)grow0 * CDIM + col] =
            make_float2(rna_tf32(acc_o[j][0] * inv0), rna_tf32(acc_o[j][1] * inv0));
        *(float2*)&y[(size_t)(grow0 + 8) * CDIM + col] =
            make_float2(rna_tf32(acc_o[j][2] * inv1), rna_tf32(acc_o[j][3] * inv1));
    }
}

// =================================================================
// launch
// =================================================================
extern "C" void kernel_launch(void* const* d_in, const int* in_sizes, int n_in,
                              void* d_out, int out_size)
{
    const float* x      = (const float*)d_in[0];
    const float* w_attn = (const float*)d_in[1];
    const float* b_attn = (const float*)d_in[2];
    const float* w_proj = (const float*)d_in[3];
    const float* b_proj = (const float*)d_in[4];
    float* out = (float*)d_out;

    float *qkv, *y, *xr, *waT, *wpT;
    cudaGetSymbolAddress((void**)&qkv, g_qkv);
    cudaGetSymbolAddress((void**)&y,   g_y);
    cudaGetSymbolAddress((void**)&xr,  g_xr);
    cudaGetSymbolAddress((void**)&waT, g_waT);
    cudaGetSymbolAddress((void**)&wpT, g_wpT);

    cudaFuncSetAttribute(tf32_gemm_kernel,
                         cudaFuncAttributeMaxDynamicSharedMemorySize, GEMM_SMEM);
    cudaFuncSetAttribute(attn_mma_kernel,
                         cudaFuncAttributeMaxDynamicSharedMemorySize, (int)ATT_SMEM);

    // 1. round x -> xr
    {
        int n4 = MROWS * CDIM / 4;
        rna_round_kernel<<<(n4 + 255) / 256, 256>>>((const float4*)x, (float4*)xr, n4);
    }
    // 2. transpose+round weights
    transpose_rna_kernel<<<dim3(C3 / 32, CDIM / 32), dim3(32, 8)>>>(w_attn, waT, CDIM, C3);
    transpose_rna_kernel<<<dim3(CDIM / 32, CDIM / 32), dim3(32, 8)>>>(w_proj, wpT, CDIM, CDIM);

    // 3. qkv = xr @ waT^T + b_attn
    tf32_gemm_kernel<<<dim3(C3 / BN, MROWS / BM), 256, GEMM_SMEM>>>(
        xr, waT, b_attn, qkv, MROWS, C3, CDIM);

    // 4. tensor-core flash attention (writes rna-rounded y)
    attn_mma_kernel<<<dim3(SEQ / 64, BATCH * NHEAD), 128, ATT_SMEM>>>(qkv, y);

    // 5. out = y @ wpT^T + b_proj
    tf32_gemm_kernel<<<dim3(CDIM / BN, MROWS / BM), 256, GEMM_SMEM>>>(
        y, wpT, b_proj, out, MROWS, CDIM, CDIM);
}

// round 11
// speedup vs baseline: 2.7544x; 1.0338x over previous
#include <cuda_runtime.h>
#include <cuda_bf16.h>
#include <cstdint>

// ---------------- problem constants ----------------
#define BATCH 4
#define SEQ   2048
#define CDIM  1024
#define NHEAD 16
#define HDIM  64
#define C3    (3*CDIM)
#define MROWS (BATCH*SEQ)   // 8192

// ---------------- scratch (device globals: allocation-free) ----------------
__device__ float g_qkv[MROWS * C3];        // [8192, 3072]
__device__ float g_y[MROWS * CDIM];        // [8192, 1024]  (rna-rounded by attention)
__device__ float g_xr[MROWS * CDIM];       // rna-rounded x
__device__ float g_waT[C3 * CDIM];         // w_attn^T [3072,1024], rna-rounded
__device__ float g_wpT[CDIM * CDIM];       // w_proj^T [1024,1024], rna-rounded

// ---------------- helpers ----------------
__device__ __forceinline__ float rna_tf32(float v) {
    uint32_t u;
    asm("cvt.rna.tf32.f32 %0, %1;" : "=r"(u) : "f"(v));
    return __uint_as_float(u);
}

__device__ __forceinline__ uint32_t smem_u32(const void* p) {
    uint32_t a;
    asm("{ .reg .u64 t; cvta.to.shared.u64 t, %1; cvt.u32.u64 %0, t; }" : "=r"(a) : "l"(p));
    return a;
}

__device__ __forceinline__ void cp_async16(uint32_t s, const void* g) {
    asm volatile("cp.async.cg.shared.global [%0], [%1], 16;" :: "r"(s), "l"(g));
}

__device__ __forceinline__ void ldsm_x4(uint32_t addr, uint32_t& r0, uint32_t& r1,
                                        uint32_t& r2, uint32_t& r3) {
    asm volatile("ldmatrix.sync.aligned.m8n8.x4.shared.b16 {%0,%1,%2,%3}, [%4];"
                 : "=r"(r0), "=r"(r1), "=r"(r2), "=r"(r3) : "r"(addr));
}

__device__ __forceinline__ void mma_tf32(float& c0, float& c1, float& c2, float& c3,
                                         uint32_t a0, uint32_t a1, uint32_t a2, uint32_t a3,
                                         uint32_t b0, uint32_t b1) {
    asm volatile(
        "mma.sync.aligned.m16n8k8.row.col.f32.tf32.tf32.f32 "
        "{%0,%1,%2,%3}, {%4,%5,%6,%7}, {%8,%9}, {%0,%1,%2,%3};"
        : "+f"(c0), "+f"(c1), "+f"(c2), "+f"(c3)
        : "r"(a0), "r"(a1), "r"(a2), "r"(a3), "r"(b0), "r"(b1));
}

// =================================================================
// tf32 mma.sync GEMM: C[M,N] = A[M,K] @ Bt[N,K]^T + bias[N]
// CTA tile 128x128, BK=64, 256 threads (8 warps, 2x4, warp 64x32).
// 3-stage cp.async pipeline + register fragment double buffering.
// Rows padded to 68 floats so ldmatrix is conflict-free.
// =================================================================
#define BM 128
#define BN 128
#define BK 64
#define APAD 68
#define TILE_BYTES (128 * APAD * 4)          // 34816 per operand tile
#define STAGE_BYTES (2 * TILE_BYTES)         // 69632
#define NSTAGE 3
#define GEMM_SMEM (NSTAGE * STAGE_BYTES)     // 208896
#define ROW_STEP_BYTES (16 * APAD * 4)       // smem bytes per 16 rows

__global__ __launch_bounds__(256, 1) void tf32_gemm_kernel(
    const float* __restrict__ A, const float* __restrict__ Bt,
    const float* __restrict__ bias, float* __restrict__ C,
    int M, int N, int K)
{
    extern __shared__ __align__(128) char smem_raw[];
    const uint32_t sbase = smem_u32(smem_raw);

    const int tid = threadIdx.x;
    const int wid = tid >> 5, lane = tid & 31;
    const int warp_m = wid >> 2;
    const int warp_n = wid & 3;
    const int m0 = blockIdx.y * BM;
    const int n0 = blockIdx.x * BN;

    // ---- cp.async mapping: thread handles rows r0+16i, fixed 16B col chunk ----
    const int r0 = tid >> 4, cc = tid & 15;
    const uint32_t s_off0 = (uint32_t)(r0 * APAD + cc * 4) * 4;
    const float* gA0 = A  + (size_t)(m0 + r0) * K + cc * 4;
    const float* gB0 = Bt + (size_t)(n0 + r0) * K + cc * 4;

    // ---- ldmatrix per-lane offsets ----
    uint32_t a_off[4];
    {
        const int r = (lane & 7) + ((lane >> 3) & 1) * 8;
        const int cg = (lane >> 4) * 4;
        #pragma unroll
        for (int i = 0; i < 4; ++i)
            a_off[i] = (uint32_t)((warp_m * 64 + 16 * i + r) * APAD + cg) * 4;
    }
    uint32_t b_off[2];
    {
        const int r = (lane & 7) + ((lane >> 4) & 1) * 8;
        const int cg = ((lane >> 3) & 1) * 4;
        #pragma unroll
        for (int p = 0; p < 2; ++p)
            b_off[p] = (uint32_t)(TILE_BYTES) +
                       (uint32_t)((warp_n * 32 + 16 * p + r) * APAD + cg) * 4;
    }

    float acc[4][4][4];
    #pragma unroll
    for (int i = 0; i < 4; ++i)
        #pragma unroll
        for (int j = 0; j < 4; ++j)
            #pragma unroll
            for (int q = 0; q < 4; ++q) acc[i][j][q] = 0.f;

    const int NT = K / BK;   // 16

    // ---- stage loader ----
    auto load_stage = [&](int t) {
        const uint32_t sb = sbase + (t % NSTAGE) * STAGE_BYTES;
        const float* a = gA0 + t * BK;
        const float* b = gB0 + t * BK;
        #pragma unroll
        for (int i = 0; i < 8; ++i) {
            cp_async16(sb + s_off0 + i * ROW_STEP_BYTES, a + (size_t)(16 * i) * K);
            cp_async16(sb + TILE_BYTES + s_off0 + i * ROW_STEP_BYTES, b + (size_t)(16 * i) * K);
        }
    };

    // ---- prologue: 2 stages in flight ----
    load_stage(0);
    asm volatile("cp.async.commit_group;");
    load_stage(1);
    asm volatile("cp.async.commit_group;");

    for (int t = 0; t < NT; ++t) {
        asm volatile("cp.async.wait_group 1;");
        __syncthreads();

        if (t + 2 < NT) load_stage(t + 2);
        asm volatile("cp.async.commit_group;");

        const uint32_t st = sbase + (t % NSTAGE) * STAGE_BYTES;

        // fragment double buffer over 8 k-steps
        uint32_t af[2][4][4], bf[2][4][2];
        #pragma unroll
        for (int i = 0; i < 4; ++i)
            ldsm_x4(st + a_off[i], af[0][i][0], af[0][i][1], af[0][i][2], af[0][i][3]);
        #pragma unroll
        for (int p = 0; p < 2; ++p)
            ldsm_x4(st + b_off[p],
                    bf[0][2*p][0], bf[0][2*p][1], bf[0][2*p+1][0], bf[0][2*p+1][1]);

        #pragma unroll
        for (int ks = 0; ks < 8; ++ks) {
            const int cur = ks & 1, nxt = cur ^ 1;
            if (ks < 7) {
                const uint32_t ko = (uint32_t)((ks + 1) * 32);
                #pragma unroll
                for (int i = 0; i < 4; ++i)
                    ldsm_x4(st + a_off[i] + ko,
                            af[nxt][i][0], af[nxt][i][1], af[nxt][i][2], af[nxt][i][3]);
                #pragma unroll
                for (int p = 0; p < 2; ++p)
                    ldsm_x4(st + b_off[p] + ko,
                            bf[nxt][2*p][0], bf[nxt][2*p][1],
                            bf[nxt][2*p+1][0], bf[nxt][2*p+1][1]);
            }
            #pragma unroll
            for (int i = 0; i < 4; ++i)
                #pragma unroll
                for (int j = 0; j < 4; ++j)
                    mma_tf32(acc[i][j][0], acc[i][j][1], acc[i][j][2], acc[i][j][3],
                             af[cur][i][0], af[cur][i][1], af[cur][i][2], af[cur][i][3],
                             bf[cur][j][0], bf[cur][j][1]);
        }
    }

    // ---- epilogue: bias + store ----
    const int g = lane >> 2, c = lane & 3;
    #pragma unroll
    for (int i = 0; i < 4; ++i) {
        const int row_a = m0 + warp_m * 64 + 16 * i + g;
        #pragma unroll
        for (int j = 0; j < 4; ++j) {
            const int col = n0 + warp_n * 32 + 8 * j + 2 * c;
            const float b0 = bias[col], b1 = bias[col + 1];
            float2 v0 = make_float2(acc[i][j][0] + b0, acc[i][j][1] + b1);
            float2 v1 = make_float2(acc[i][j][2] + b0, acc[i][j][3] + b1);
            *(float2*)&C[(size_t)row_a * N + col]       = v0;
            *(float2*)&C[(size_t)(row_a + 8) * N + col] = v1;
        }
    }
}

// =================================================================
// pre-pass kernels (unchanged)
// =================================================================
__global__ __launch_bounds__(256) void rna_round_kernel(
    const float4* __restrict__ in, float4* __restrict__ out, int n4)
{
    int i = blockIdx.x * 256 + threadIdx.x;
    if (i < n4) {
        float4 v = in[i];
        v.x = rna_tf32(v.x); v.y = rna_tf32(v.y);
        v.z = rna_tf32(v.z); v.w = rna_tf32(v.w);
        out[i] = v;
    }
}

__global__ __launch_bounds__(256) void transpose_rna_kernel(
    const float* __restrict__ in, float* __restrict__ out, int K, int N)
{
    __shared__ float tile[32][33];
    const int k0 = blockIdx.y * 32, n0 = blockIdx.x * 32;
    const int tx = threadIdx.x, ty = threadIdx.y;
    #pragma unroll
    for (int i = 0; i < 32; i += 8)
        tile[ty + i][tx] = in[(size_t)(k0 + ty + i) * N + n0 + tx];
    __syncthreads();
    #pragma unroll
    for (int i = 0; i < 32; i += 8)
        out[(size_t)(n0 + ty + i) * K + k0 + tx] = rna_tf32(tile[tx][ty + i]);
}

// =================================================================
// Tensor-core flash attention (tf32 mma.sync), fp32 softmax, causal.
// Block: (b,h,128-row q tile), 256 threads / 8 warps; warp w owns q
// rows [16w,16w+16). KV tiles of 64 rows amortized over 128 q rows.
//   sQ [128 q][68 hd]   A-operand of S     (pre-scaled, rna)
//   sK [64 kv][68 hd]   B-operand of S     (K-major, rna)
//   sVT[64 hd][68 kv]   B-operand of P@V   (V transposed, rna)
//   sP [128 q][68 kv]   A-operand of P@V   (per-warp-disjoint rows)
// =================================================================
#define FPAD 68
#define QROWS 128
#define SQ_BYTES (QROWS * FPAD * 4)     // 34816
#define SK_BYTES (64 * FPAD * 4)        // 17408
#define ATT_SMEM (SQ_BYTES + 2 * SK_BYTES + SQ_BYTES)   // 104448

__global__ __launch_bounds__(256) void attn_mma_kernel(
    const float* __restrict__ qkv, float* __restrict__ y)
{
    extern __shared__ __align__(16) float sm[];
    float* sQ  = sm;                                  // 128 x 68
    float* sK  = sm + QROWS * FPAD;                   // 64 x 68
    float* sVT = sm + QROWS * FPAD + 64 * FPAD;       // 64 x 68
    float* sP  = sm + QROWS * FPAD + 2 * 64 * FPAD;   // 128 x 68

    const int tid = threadIdx.x;
    const int wid = tid >> 5, lane = tid & 31;
    const int qt = blockIdx.x;             // q tile 0..15 (128 rows each)
    const int bh = blockIdx.y;
    const int b = bh >> 4, h = bh & 15;
    const int qbase = qt * QROWS;
    const int rowbase = b * SEQ;

    const uint32_t sbase = smem_u32(sm);

    // ldmatrix per-lane offsets (validated mappings)
    const int ar  = (lane & 7) + ((lane >> 3) & 1) * 8;
    const int acg = (lane >> 4) * 4;
    const uint32_t aoffQ = sbase + (uint32_t)((wid * 16 + ar) * FPAD + acg) * 4;
    const uint32_t aoffP = sbase + (uint32_t)(SQ_BYTES + 2 * SK_BYTES) +
                           (uint32_t)((wid * 16 + ar) * FPAD + acg) * 4;

    const int br  = (lane & 7) + ((lane >> 4) & 1) * 8;
    const int bcg = ((lane >> 3) & 1) * 4;
    uint32_t boffK[4], boffV[4];
    #pragma unroll
    for (int p = 0; p < 4; ++p) {
        boffK[p] = sbase + (uint32_t)SQ_BYTES +
                   (uint32_t)((16 * p + br) * FPAD + bcg) * 4;
        boffV[p] = sbase + (uint32_t)(SQ_BYTES + SK_BYTES) +
                   (uint32_t)((16 * p + br) * FPAD + bcg) * 4;
    }

    // ---- load Q (scaled by 1/sqrt(hd), rna-rounded): 128 rows ----
    for (int u = tid; u < QROWS * 16; u += 256) {
        const int row = u >> 4, c4 = (u & 15) << 2;
        float4 qv = *(const float4*)&qkv[(size_t)(rowbase + qbase + row) * C3 + h * HDIM + c4];
        float4 o;
        o.x = rna_tf32(qv.x * 0.125f); o.y = rna_tf32(qv.y * 0.125f);
        o.z = rna_tf32(qv.z * 0.125f); o.w = rna_tf32(qv.w * 0.125f);
        *(float4*)&sQ[row * FPAD + c4] = o;
    }

    // softmax state + output accumulators
    float m0 = -1e30f, m1 = -1e30f, l0 = 0.f, l1 = 0.f;
    float acc_o[8][4];
    #pragma unroll
    for (int j = 0; j < 8; ++j)
        #pragma unroll
        for (int q = 0; q < 4; ++q) acc_o[j][q] = 0.f;

    const int g = lane >> 2, c = lane & 3;
    const int njt = 2 * qt + 2;            // KV tiles of 64 rows

    for (int jt = 0; jt < njt; ++jt) {
        __syncthreads();   // prev iter done with sK/sVT (and sQ visible on jt=0)

        // ---- load K (K-major) + V (transposed), rna-rounded: 64 rows ----
        for (int u = tid; u < 64 * 16; u += 256) {
            const int row = u >> 4, c4 = (u & 15) << 2;
            const float* kp = &qkv[(size_t)(rowbase + jt * 64 + row) * C3 + CDIM + h * HDIM + c4];
            float4 kv4 = *(const float4*)kp;
            float4 ko;
            ko.x = rna_tf32(kv4.x); ko.y = rna_tf32(kv4.y);
            ko.z = rna_tf32(kv4.z); ko.w = rna_tf32(kv4.w);
            *(float4*)&sK[row * FPAD + c4] = ko;
            float4 vv4 = *(const float4*)(kp + CDIM);
            sVT[(c4 + 0) * FPAD + row] = rna_tf32(vv4.x);
            sVT[(c4 + 1) * FPAD + row] = rna_tf32(vv4.y);
            sVT[(c4 + 2) * FPAD + row] = rna_tf32(vv4.z);
            sVT[(c4 + 3) * FPAD + row] = rna_tf32(vv4.w);
        }
        __syncthreads();

        // ---- S = Q @ K^T ----
        float s[8][4];
        #pragma unroll
        for (int j = 0; j < 8; ++j)
            #pragma unroll
            for (int q = 0; q < 4; ++q) s[j][q] = 0.f;

        #pragma unroll
        for (int ks = 0; ks < 8; ++ks) {
            const uint32_t ko = (uint32_t)(ks * 32);
            uint32_t a0, a1, a2, a3;
            ldsm_x4(aoffQ + ko, a0, a1, a2, a3);
            uint32_t bfr[8][2];
            #pragma unroll
            for (int p = 0; p < 4; ++p)
                ldsm_x4(boffK[p] + ko, bfr[2*p][0], bfr[2*p][1], bfr[2*p+1][0], bfr[2*p+1][1]);
            #pragma unroll
            for (int j = 0; j < 8; ++j)
                mma_tf32(s[j][0], s[j][1], s[j][2], s[j][3],
                         a0, a1, a2, a3, bfr[j][0], bfr[j][1]);
        }

        // ---- causal mask (two diagonal tiles: jt >= 2*qt) ----
        if (jt >= 2 * qt) {
            const int cbase = 64 * jt - QROWS * qt;    // 0 or 64
            const int r0 = wid * 16 + g;               // relative q row
            const int r1 = r0 + 8;
            #pragma unroll
            for (int j = 0; j < 8; ++j) {
                const int col = cbase + 8 * j + 2 * c;
                if (col     > r0) s[j][0] = -1e30f;
                if (col + 1 > r0) s[j][1] = -1e30f;
                if (col     > r1) s[j][2] = -1e30f;
                if (col + 1 > r1) s[j][3] = -1e30f;
            }
        }

        // ---- online softmax (quad-lane row reduction) ----
        float mx0 = -1e30f, mx1 = -1e30f;
        #pragma unroll
        for (int j = 0; j < 8; ++j) {
            mx0 = fmaxf(mx0, fmaxf(s[j][0], s[j][1]));
            mx1 = fmaxf(mx1, fmaxf(s[j][2], s[j][3]));
        }
        mx0 = fmaxf(mx0, __shfl_xor_sync(0xffffffffu, mx0, 1));
        mx0 = fmaxf(mx0, __shfl_xor_sync(0xffffffffu, mx0, 2));
        mx1 = fmaxf(mx1, __shfl_xor_sync(0xffffffffu, mx1, 1));
        mx1 = fmaxf(mx1, __shfl_xor_sync(0xffffffffu, mx1, 2));

        const float mn0 = fmaxf(m0, mx0), mn1 = fmaxf(m1, mx1);
        const float corr0 = __expf(m0 - mn0), corr1 = __expf(m1 - mn1);
        float sum0 = 0.f, sum1 = 0.f;
        #pragma unroll
        for (int j = 0; j < 8; ++j) {
            s[j][0] = __expf(s[j][0] - mn0);
            s[j][1] = __expf(s[j][1] - mn0);
            s[j][2] = __expf(s[j][2] - mn1);
            s[j][3] = __expf(s[j][3] - mn1);
            sum0 += s[j][0] + s[j][1];
            sum1 += s[j][2] + s[j][3];
        }
        sum0 += __shfl_xor_sync(0xffffffffu, sum0, 1);
        sum0 += __shfl_xor_sync(0xffffffffu, sum0, 2);
        sum1 += __shfl_xor_sync(0xffffffffu, sum1, 1);
        sum1 += __shfl_xor_sync(0xffffffffu, sum1, 2);

        l0 = l0 * corr0 + sum0;  m0 = mn0;
        l1 = l1 * corr1 + sum1;  m1 = mn1;
        #pragma unroll
        for (int j = 0; j < 8; ++j) {
            acc_o[j][0] *= corr0; acc_o[j][1] *= corr0;
            acc_o[j][2] *= corr1; acc_o[j][3] *= corr1;
        }

        // ---- P -> smem (rna), per-warp-disjoint rows ----
        {
            float* p0 = &sP[(wid * 16 + g) * FPAD + 2 * c];
            float* p1 = &sP[(wid * 16 + 8 + g) * FPAD + 2 * c];
            #pragma unroll
            for (int j = 0; j < 8; ++j) {
                *(float2*)(p0 + 8 * j) = make_float2(rna_tf32(s[j][0]), rna_tf32(s[j][1]));
                *(float2*)(p1 + 8 * j) = make_float2(rna_tf32(s[j][2]), rna_tf32(s[j][3]));
            }
        }
        __syncwarp();

        // ---- O += P @ V  (A = sP, B = sVT, k = kv) ----
        #pragma unroll
        for (int ks = 0; ks < 8; ++ks) {
            const uint32_t ko = (uint32_t)(ks * 32);
            uint32_t a0, a1, a2, a3;
            ldsm_x4(aoffP + ko, a0, a1, a2, a3);
            uint32_t bfr[8][2];
            #pragma unroll
            for (int p = 0; p < 4; ++p)
                ldsm_x4(boffV[p] + ko, bfr[2*p][0], bfr[2*p][1], bfr[2*p+1][0], bfr[2*p+1][1]);
            #pragma unroll
            for (int j = 0; j < 8; ++j)
                mma_tf32(acc_o[j][0], acc_o[j][1], acc_o[j][2], acc_o[j][3],
                         a0, a1, a2, a3, bfr[j][0], bfr[j][1]);
        }
    }

    // ---- finalize + store y (rna-rounded for the proj GEMM) ----
    const float inv0 = 1.f / l0, inv1 = 1.f / l1;
    const int grow0 = rowbase + qbase + wid * 16 + g;
    #pragma unroll
    for (int j = 0; j < 8; ++j) {
        const int col = h * HDIM + 8 * j + 2 * c;
        *(float2*)&y[(size_t)grow0 * CDIM + col] =
            make_float2(rna_tf32(acc_o[j][0] * inv0), rna_tf32(acc_o[j][1] * inv0));
        *(float2*)&y[(size_t)(grow0 + 8) * CDIM + col] =
            make_float2(rna_tf32(acc_o[j][2] * inv1), rna_tf32(acc_o[j][3] * inv1));
    }
}

// =================================================================
// launch
// =================================================================
extern "C" void kernel_launch(void* const* d_in, const int* in_sizes, int n_in,
                              void* d_out, int out_size)
{
    const float* x      = (const float*)d_in[0];
    const float* w_attn = (const float*)d_in[1];
    const float* b_attn = (const float*)d_in[2];
    const float* w_proj = (const float*)d_in[3];
    const float* b_proj = (const float*)d_in[4];
    float* out = (float*)d_out;

    float *qkv, *y, *xr, *waT, *wpT;
    cudaGetSymbolAddress((void**)&qkv, g_qkv);
    cudaGetSymbolAddress((void**)&y,   g_y);
    cudaGetSymbolAddress((void**)&xr,  g_xr);
    cudaGetSymbolAddress((void**)&waT, g_waT);
    cudaGetSymbolAddress((void**)&wpT, g_wpT);

    cudaFuncSetAttribute(tf32_gemm_kernel,
                         cudaFuncAttributeMaxDynamicSharedMemorySize, GEMM_SMEM);
    cudaFuncSetAttribute(attn_mma_kernel,
                         cudaFuncAttributeMaxDynamicSharedMemorySize, (int)ATT_SMEM);

    // 1. round x -> xr
    {
        int n4 = MROWS * CDIM / 4;
        rna_round_kernel<<<(n4 + 255) / 256, 256>>>((const float4*)x, (float4*)xr, n4);
    }
    // 2. transpose+round weights
    transpose_rna_kernel<<<dim3(C3 / 32, CDIM / 32), dim3(32, 8)>>>(w_attn, waT, CDIM, C3);
    transpose_rna_kernel<<<dim3(CDIM / 32, CDIM / 32), dim3(32, 8)>>>(w_proj, wpT, CDIM, CDIM);

    // 3. qkv = xr @ waT^T + b_attn
    tf32_gemm_kernel<<<dim3(C3 / BN, MROWS / BM), 256, GEMM_SMEM>>>(
        xr, waT, b_attn, qkv, MROWS, C3, CDIM);

    // 4. tensor-core flash attention (writes rna-rounded y)
    attn_mma_kernel<<<dim3(SEQ / QROWS, BATCH * NHEAD), 256, ATT_SMEM>>>(qkv, y);

    // 5. out = y @ wpT^T + b_proj
    tf32_gemm_kernel<<<dim3(CDIM / BN, MROWS / BM), 256, GEMM_SMEM>>>(
        y, wpT, b_proj, out, MROWS, CDIM, CDIM);
}

// round 13
// speedup vs baseline: 2.7575x; 1.0011x over previous
#include <cuda_runtime.h>
#include <cuda_bf16.h>
#include <cstdint>

// ---------------- problem constants ----------------
#define BATCH 4
#define SEQ   2048
#define CDIM  1024
#define NHEAD 16
#define HDIM  64
#define C3    (3*CDIM)
#define MROWS (BATCH*SEQ)   // 8192

// ---------------- scratch (device globals: allocation-free) ----------------
__device__ float g_qkv[MROWS * C3];        // [8192, 3072]
__device__ float g_y[MROWS * CDIM];        // [8192, 1024]
__device__ float g_waT[C3 * CDIM];         // w_attn^T [3072,1024]
__device__ float g_wpT[CDIM * CDIM];       // w_proj^T [1024,1024]

// ---------------- helpers ----------------
__device__ __forceinline__ float rna_tf32(float v) {
    uint32_t u;
    asm("cvt.rna.tf32.f32 %0, %1;" : "=r"(u) : "f"(v));
    return __uint_as_float(u);
}

__device__ __forceinline__ uint32_t rna_u32(uint32_t r) {
    uint32_t u;
    asm("cvt.rna.tf32.f32 %0, %1;" : "=r"(u) : "f"(__uint_as_float(r)));
    return u;
}

__device__ __forceinline__ uint32_t smem_u32(const void* p) {
    uint32_t a;
    asm("{ .reg .u64 t; cvta.to.shared.u64 t, %1; cvt.u32.u64 %0, t; }" : "=r"(a) : "l"(p));
    return a;
}

__device__ __forceinline__ void cp_async16(uint32_t s, const void* g) {
    asm volatile("cp.async.cg.shared.global [%0], [%1], 16;" :: "r"(s), "l"(g));
}

__device__ __forceinline__ void ldsm_x4(uint32_t addr, uint32_t& r0, uint32_t& r1,
                                        uint32_t& r2, uint32_t& r3) {
    asm volatile("ldmatrix.sync.aligned.m8n8.x4.shared.b16 {%0,%1,%2,%3}, [%4];"
                 : "=r"(r0), "=r"(r1), "=r"(r2), "=r"(r3) : "r"(addr));
}

__device__ __forceinline__ void mma_tf32(float& c0, float& c1, float& c2, float& c3,
                                         uint32_t a0, uint32_t a1, uint32_t a2, uint32_t a3,
                                         uint32_t b0, uint32_t b1) {
    asm volatile(
        "mma.sync.aligned.m16n8k8.row.col.f32.tf32.tf32.f32 "
        "{%0,%1,%2,%3}, {%4,%5,%6,%7}, {%8,%9}, {%0,%1,%2,%3};"
        : "+f"(c0), "+f"(c1), "+f"(c2), "+f"(c3)
        : "r"(a0), "r"(a1), "r"(a2), "r"(a3), "r"(b0), "r"(b1));
}

// =================================================================
// tf32 mma.sync GEMM: C[M,N] = A[M,K] @ Bt[N,K]^T + bias[N]
// CTA tile 128x256, BK=32, 256 threads (8 warps, 2x4, warp 64x64).
// 3-stage cp.async pipeline; rna-rounding applied IN REGISTERS on
// fragments (inputs need no pre-rounding). Rows padded to 36 floats.
// =================================================================
#define BM 128
#define BN 256
#define BK 32
#define APAD 36
#define TILE_A_BYTES (128 * APAD * 4)        // 18432
#define TILE_B_BYTES (256 * APAD * 4)        // 36864
#define STAGE_BYTES (TILE_A_BYTES + TILE_B_BYTES)  // 55296
#define NSTAGE 3
#define GEMM_SMEM (NSTAGE * STAGE_BYTES)     // 165888

__global__ __launch_bounds__(256, 1) void tf32_gemm_kernel(
    const float* __restrict__ A, const float* __restrict__ Bt,
    const float* __restrict__ bias, float* __restrict__ C,
    int M, int N, int K)
{
    extern __shared__ __align__(128) char smem_raw[];
    const uint32_t sbase = smem_u32(smem_raw);

    const int tid = threadIdx.x;
    const int wid = tid >> 5, lane = tid & 31;
    const int warp_m = wid >> 2;         // 0..1 -> 64-row half
    const int warp_n = wid & 3;          // 0..3 -> 64-col slice
    const int m0 = blockIdx.y * BM;
    const int n0 = blockIdx.x * BN;

    // ---- cp.async chunk mapping ----
    // A: 128x32 floats = 1024 16B chunks, 4 per thread
    // B: 256x32 floats = 2048 16B chunks, 8 per thread
    uint32_t sa_off[4], sb_off[8];
    const float* gA[4];
    const float* gB[8];
    #pragma unroll
    for (int i = 0; i < 4; ++i) {
        const int u = tid + 256 * i;
        const int row = u >> 3, cc = u & 7;
        sa_off[i] = (uint32_t)(row * APAD + cc * 4) * 4;
        gA[i] = A + (size_t)(m0 + row) * K + cc * 4;
    }
    #pragma unroll
    for (int i = 0; i < 8; ++i) {
        const int u = tid + 256 * i;
        const int row = u >> 3, cc = u & 7;
        sb_off[i] = (uint32_t)TILE_A_BYTES + (uint32_t)(row * APAD + cc * 4) * 4;
        gB[i] = Bt + (size_t)(n0 + row) * K + cc * 4;
    }

    // ---- ldmatrix per-lane offsets ----
    uint32_t a_off[4];
    {
        const int r = (lane & 7) + ((lane >> 3) & 1) * 8;
        const int cg = (lane >> 4) * 4;
        #pragma unroll
        for (int i = 0; i < 4; ++i)
            a_off[i] = (uint32_t)((warp_m * 64 + 16 * i + r) * APAD + cg) * 4;
    }
    uint32_t b_off[4];
    {
        const int r = (lane & 7) + ((lane >> 4) & 1) * 8;
        const int cg = ((lane >> 3) & 1) * 4;
        #pragma unroll
        for (int p = 0; p < 4; ++p)
            b_off[p] = (uint32_t)TILE_A_BYTES +
                       (uint32_t)((warp_n * 64 + 16 * p + r) * APAD + cg) * 4;
    }

    float acc[4][8][4];
    #pragma unroll
    for (int i = 0; i < 4; ++i)
        #pragma unroll
        for (int j = 0; j < 8; ++j)
            #pragma unroll
            for (int q = 0; q < 4; ++q) acc[i][j][q] = 0.f;

    const int NT = K / BK;   // 32

    auto load_stage = [&](int t) {
        const uint32_t sb = sbase + (t % NSTAGE) * STAGE_BYTES;
        #pragma unroll
        for (int i = 0; i < 4; ++i) cp_async16(sb + sa_off[i], gA[i] + t * BK);
        #pragma unroll
        for (int i = 0; i < 8; ++i) cp_async16(sb + sb_off[i], gB[i] + t * BK);
    };

    // ---- prologue: 2 stages in flight ----
    load_stage(0);
    asm volatile("cp.async.commit_group;");
    load_stage(1);
    asm volatile("cp.async.commit_group;");

    for (int t = 0; t < NT; ++t) {
        asm volatile("cp.async.wait_group 1;");
        __syncthreads();

        if (t + 2 < NT) load_stage(t + 2);
        asm volatile("cp.async.commit_group;");

        const uint32_t st = sbase + (t % NSTAGE) * STAGE_BYTES;
        #pragma unroll
        for (int ks = 0; ks < 4; ++ks) {
            const uint32_t ko = (uint32_t)(ks * 32);   // 8 floats per k-step
            uint32_t af[4][4], bfr[8][2];
            #pragma unroll
            for (int i = 0; i < 4; ++i) {
                ldsm_x4(st + a_off[i] + ko, af[i][0], af[i][1], af[i][2], af[i][3]);
                af[i][0] = rna_u32(af[i][0]); af[i][1] = rna_u32(af[i][1]);
                af[i][2] = rna_u32(af[i][2]); af[i][3] = rna_u32(af[i][3]);
            }
            #pragma unroll
            for (int p = 0; p < 4; ++p) {
                ldsm_x4(st + b_off[p] + ko,
                        bfr[2*p][0], bfr[2*p][1], bfr[2*p+1][0], bfr[2*p+1][1]);
                bfr[2*p][0]   = rna_u32(bfr[2*p][0]);   bfr[2*p][1]   = rna_u32(bfr[2*p][1]);
                bfr[2*p+1][0] = rna_u32(bfr[2*p+1][0]); bfr[2*p+1][1] = rna_u32(bfr[2*p+1][1]);
            }
            #pragma unroll
            for (int i = 0; i < 4; ++i)
                #pragma unroll
                for (int j = 0; j < 8; ++j)
                    mma_tf32(acc[i][j][0], acc[i][j][1], acc[i][j][2], acc[i][j][3],
                             af[i][0], af[i][1], af[i][2], af[i][3],
                             bfr[j][0], bfr[j][1]);
        }
    }

    // ---- epilogue: bias + store ----
    const int g = lane >> 2, c = lane & 3;
    #pragma unroll
    for (int i = 0; i < 4; ++i) {
        const int row_a = m0 + warp_m * 64 + 16 * i + g;
        #pragma unroll
        for (int j = 0; j < 8; ++j) {
            const int col = n0 + warp_n * 64 + 8 * j + 2 * c;
            const float b0 = bias[col], b1 = bias[col + 1];
            float2 v0 = make_float2(acc[i][j][0] + b0, acc[i][j][1] + b1);
            float2 v1 = make_float2(acc[i][j][2] + b0, acc[i][j][3] + b1);
            *(float2*)&C[(size_t)row_a * N + col]       = v0;
            *(float2*)&C[(size_t)(row_a + 8) * N + col] = v1;
        }
    }
}

// =================================================================
// pre-pass: transpose only (rounding now happens in-register in GEMM)
// =================================================================
__global__ __launch_bounds__(256) void transpose_kernel(
    const float* __restrict__ in, float* __restrict__ out, int K, int N)
{
    __shared__ float tile[32][33];
    const int k0 = blockIdx.y * 32, n0 = blockIdx.x * 32;
    const int tx = threadIdx.x, ty = threadIdx.y;
    #pragma unroll
    for (int i = 0; i < 32; i += 8)
        tile[ty + i][tx] = in[(size_t)(k0 + ty + i) * N + n0 + tx];
    __syncthreads();
    #pragma unroll
    for (int i = 0; i < 32; i += 8)
        out[(size_t)(n0 + ty + i) * K + k0 + tx] = tile[tx][ty + i];
}

// =================================================================
// Tensor-core flash attention (tf32 mma.sync), fp32 softmax, causal.
// Block: (b,h,128-row q tile), 256 threads / 8 warps; 2 CTAs/SM.
//   sQ [128 q][68 hd]   A-operand of S     (pre-scaled, rna)
//   sK [64 kv][68 hd]   B-operand of S     (K-major, rna)
//   sVT[64 hd][68 kv]   B-operand of P@V   (V transposed, rna)
//   sP [128 q][68 kv]   A-operand of P@V   (per-warp-disjoint rows)
// =================================================================
#define FPAD 68
#define QROWS 128
#define SQ_BYTES (QROWS * FPAD * 4)     // 34816
#define SK_BYTES (64 * FPAD * 4)        // 17408
#define ATT_SMEM (SQ_BYTES + 2 * SK_BYTES + SQ_BYTES)   // 104448

__global__ __launch_bounds__(256, 2) void attn_mma_kernel(
    const float* __restrict__ qkv, float* __restrict__ y)
{
    extern __shared__ __align__(16) float sm[];
    float* sQ  = sm;                                  // 128 x 68
    float* sK  = sm + QROWS * FPAD;                   // 64 x 68
    float* sVT = sm + QROWS * FPAD + 64 * FPAD;       // 64 x 68
    float* sP  = sm + QROWS * FPAD + 2 * 64 * FPAD;   // 128 x 68

    const int tid = threadIdx.x;
    const int wid = tid >> 5, lane = tid & 31;
    const int qt = blockIdx.x;             // q tile 0..15 (128 rows each)
    const int bh = blockIdx.y;
    const int b = bh >> 4, h = bh & 15;
    const int qbase = qt * QROWS;
    const int rowbase = b * SEQ;

    const uint32_t sbase = smem_u32(sm);

    const int ar  = (lane & 7) + ((lane >> 3) & 1) * 8;
    const int acg = (lane >> 4) * 4;
    const uint32_t aoffQ = sbase + (uint32_t)((wid * 16 + ar) * FPAD + acg) * 4;
    const uint32_t aoffP = sbase + (uint32_t)(SQ_BYTES + 2 * SK_BYTES) +
                           (uint32_t)((wid * 16 + ar) * FPAD + acg) * 4;

    const int br  = (lane & 7) + ((lane >> 4) & 1) * 8;
    const int bcg = ((lane >> 3) & 1) * 4;
    uint32_t boffK[4], boffV[4];
    #pragma unroll
    for (int p = 0; p < 4; ++p) {
        boffK[p] = sbase + (uint32_t)SQ_BYTES +
                   (uint32_t)((16 * p + br) * FPAD + bcg) * 4;
        boffV[p] = sbase + (uint32_t)(SQ_BYTES + SK_BYTES) +
                   (uint32_t)((16 * p + br) * FPAD + bcg) * 4;
    }

    // ---- load Q (scaled by 1/sqrt(hd), rna-rounded): 128 rows ----
    for (int u = tid; u < QROWS * 16; u += 256) {
        const int row = u >> 4, c4 = (u & 15) << 2;
        float4 qv = *(const float4*)&qkv[(size_t)(rowbase + qbase + row) * C3 + h * HDIM + c4];
        float4 o;
        o.x = rna_tf32(qv.x * 0.125f); o.y = rna_tf32(qv.y * 0.125f);
        o.z = rna_tf32(qv.z * 0.125f); o.w = rna_tf32(qv.w * 0.125f);
        *(float4*)&sQ[row * FPAD + c4] = o;
    }

    float m0 = -1e30f, m1 = -1e30f, l0 = 0.f, l1 = 0.f;
    float acc_o[8][4];
    #pragma unroll
    for (int j = 0; j < 8; ++j)
        #pragma unroll
        for (int q = 0; q < 4; ++q) acc_o[j][q] = 0.f;

    const int g = lane >> 2, c = lane & 3;
    const int njt = 2 * qt + 2;            // KV tiles of 64 rows

    for (int jt = 0; jt < njt; ++jt) {
        __syncthreads();

        // ---- load K (K-major) + V (transposed), rna-rounded: 64 rows ----
        for (int u = tid; u < 64 * 16; u += 256) {
            const int row = u >> 4, c4 = (u & 15) << 2;
            const float* kp = &qkv[(size_t)(rowbase + jt * 64 + row) * C3 + CDIM + h * HDIM + c4];
            float4 kv4 = *(const float4*)kp;
            float4 ko;
            ko.x = rna_tf32(kv4.x); ko.y = rna_tf32(kv4.y);
            ko.z = rna_tf32(kv4.z); ko.w = rna_tf32(kv4.w);
            *(float4*)&sK[row * FPAD + c4] = ko;
            float4 vv4 = *(const float4*)(kp + CDIM);
            sVT[(c4 + 0) * FPAD + row] = rna_tf32(vv4.x);
            sVT[(c4 + 1) * FPAD + row] = rna_tf32(vv4.y);
            sVT[(c4 + 2) * FPAD + row] = rna_tf32(vv4.z);
            sVT[(c4 + 3) * FPAD + row] = rna_tf32(vv4.w);
        }
        __syncthreads();

        // ---- S = Q @ K^T ----
        float s[8][4];
        #pragma unroll
        for (int j = 0; j < 8; ++j)
            #pragma unroll
            for (int q = 0; q < 4; ++q) s[j][q] = 0.f;

        #pragma unroll
        for (int ks = 0; ks < 8; ++ks) {
            const uint32_t ko = (uint32_t)(ks * 32);
            uint32_t a0, a1, a2, a3;
            ldsm_x4(aoffQ + ko, a0, a1, a2, a3);
            uint32_t bfr[8][2];
            #pragma unroll
            for (int p = 0; p < 4; ++p)
                ldsm_x4(boffK[p] + ko, bfr[2*p][0], bfr[2*p][1], bfr[2*p+1][0], bfr[2*p+1][1]);
            #pragma unroll
            for (int j = 0; j < 8; ++j)
                mma_tf32(s[j][0], s[j][1], s[j][2], s[j][3],
                         a0, a1, a2, a3, bfr[j][0], bfr[j][1]);
        }

        // ---- causal mask (two diagonal tiles: jt >= 2*qt) ----
        if (jt >= 2 * qt) {
            const int cbase = 64 * jt - QROWS * qt;    // 0 or 64
            const int r0 = wid * 16 + g;
            const int r1 = r0 + 8;
            #pragma unroll
            for (int j = 0; j < 8; ++j) {
                const int col = cbase + 8 * j + 2 * c;
                if (col     > r0) s[j][0] = -1e30f;
                if (col + 1 > r0) s[j][1] = -1e30f;
                if (col     > r1) s[j][2] = -1e30f;
                if (col + 1 > r1) s[j][3] = -1e30f;
            }
        }

        // ---- online softmax (quad-lane row reduction) ----
        float mx0 = -1e30f, mx1 = -1e30f;
        #pragma unroll
        for (int j = 0; j < 8; ++j) {
            mx0 = fmaxf(mx0, fmaxf(s[j][0], s[j][1]));
            mx1 = fmaxf(mx1, fmaxf(s[j][2], s[j][3]));
        }
        mx0 = fmaxf(mx0, __shfl_xor_sync(0xffffffffu, mx0, 1));
        mx0 = fmaxf(mx0, __shfl_xor_sync(0xffffffffu, mx0, 2));
        mx1 = fmaxf(mx1, __shfl_xor_sync(0xffffffffu, mx1, 1));
        mx1 = fmaxf(mx1, __shfl_xor_sync(0xffffffffu, mx1, 2));

        const float mn0 = fmaxf(m0, mx0), mn1 = fmaxf(m1, mx1);
        const float corr0 = __expf(m0 - mn0), corr1 = __expf(m1 - mn1);
        float sum0 = 0.f, sum1 = 0.f;
        #pragma unroll
        for (int j = 0; j < 8; ++j) {
            s[j][0] = __expf(s[j][0] - mn0);
            s[j][1] = __expf(s[j][1] - mn0);
            s[j][2] = __expf(s[j][2] - mn1);
            s[j][3] = __expf(s[j][3] - mn1);
            sum0 += s[j][0] + s[j][1];
            sum1 += s[j][2] + s[j][3];
        }
        sum0 += __shfl_xor_sync(0xffffffffu, sum0, 1);
        sum0 += __shfl_xor_sync(0xffffffffu, sum0, 2);
        sum1 += __shfl_xor_sync(0xffffffffu, sum1, 1);
        sum1 += __shfl_xor_sync(0xffffffffu, sum1, 2);

        l0 = l0 * corr0 + sum0;  m0 = mn0;
        l1 = l1 * corr1 + sum1;  m1 = mn1;
        #pragma unroll
        for (int j = 0; j < 8; ++j) {
            acc_o[j][0] *= corr0; acc_o[j][1] *= corr0;
            acc_o[j][2] *= corr1; acc_o[j][3] *= corr1;
        }

        // ---- P -> smem (rna), per-warp-disjoint rows ----
        {
            float* p0 = &sP[(wid * 16 + g) * FPAD + 2 * c];
            float* p1 = &sP[(wid * 16 + 8 + g) * FPAD + 2 * c];
            #pragma unroll
            for (int j = 0; j < 8; ++j) {
                *(float2*)(p0 + 8 * j) = make_float2(rna_tf32(s[j][0]), rna_tf32(s[j][1]));
                *(float2*)(p1 + 8 * j) = make_float2(rna_tf32(s[j][2]), rna_tf32(s[j][3]));
            }
        }
        __syncwarp();

        // ---- O += P @ V ----
        #pragma unroll
        for (int ks = 0; ks < 8; ++ks) {
            const uint32_t ko = (uint32_t)(ks * 32);
            uint32_t a0, a1, a2, a3;
            ldsm_x4(aoffP + ko, a0, a1, a2, a3);
            uint32_t bfr[8][2];
            #pragma unroll
            for (int p = 0; p < 4; ++p)
                ldsm_x4(boffV[p] + ko, bfr[2*p][0], bfr[2*p][1], bfr[2*p+1][0], bfr[2*p+1][1]);
            #pragma unroll
            for (int j = 0; j < 8; ++j)
                mma_tf32(acc_o[j][0], acc_o[j][1], acc_o[j][2], acc_o[j][3],
                         a0, a1, a2, a3, bfr[j][0], bfr[j][1]);
        }
    }

    // ---- finalize + store y (GEMM2 rounds in-register; plain fp32 here) ----
    const float inv0 = 1.f / l0, inv1 = 1.f / l1;
    const int grow0 = rowbase + qbase + wid * 16 + g;
    #pragma unroll
    for (int j = 0; j < 8; ++j) {
        const int col = h * HDIM + 8 * j + 2 * c;
        *(float2*)&y[(size_t)grow0 * CDIM + col] =
            make_float2(acc_o[j][0] * inv0, acc_o[j][1] * inv0);
        *(float2*)&y[(size_t)(grow0 + 8) * CDIM + col] =
            make_float2(acc_o[j][2] * inv1, acc_o[j][3] * inv1);
    }
}

// =================================================================
// launch
// =================================================================
extern "C" void kernel_launch(void* const* d_in, const int* in_sizes, int n_in,
                              void* d_out, int out_size)
{
    const float* x      = (const float*)d_in[0];
    const float* w_attn = (const float*)d_in[1];
    const float* b_attn = (const float*)d_in[2];
    const float* w_proj = (const float*)d_in[3];
    const float* b_proj = (const float*)d_in[4];
    float* out = (float*)d_out;

    float *qkv, *y, *waT, *wpT;
    cudaGetSymbolAddress((void**)&qkv, g_qkv);
    cudaGetSymbolAddress((void**)&y,   g_y);
    cudaGetSymbolAddress((void**)&waT, g_waT);
    cudaGetSymbolAddress((void**)&wpT, g_wpT);

    cudaFuncSetAttribute(tf32_gemm_kernel,
                         cudaFuncAttributeMaxDynamicSharedMemorySize, GEMM_SMEM);
    cudaFuncSetAttribute(attn_mma_kernel,
                         cudaFuncAttributeMaxDynamicSharedMemorySize, (int)ATT_SMEM);

    // 1. transpose weights (rounding happens in-register in the GEMM)
    transpose_kernel<<<dim3(C3 / 32, CDIM / 32), dim3(32, 8)>>>(w_attn, waT, CDIM, C3);
    transpose_kernel<<<dim3(CDIM / 32, CDIM / 32), dim3(32, 8)>>>(w_proj, wpT, CDIM, CDIM);

    // 2. qkv = x @ waT^T + b_attn   (x read directly; rna in-register)
    tf32_gemm_kernel<<<dim3(C3 / BN, MROWS / BM), 256, GEMM_SMEM>>>(
        x, waT, b_attn, qkv, MROWS, C3, CDIM);

    // 3. tensor-core flash attention
    attn_mma_kernel<<<dim3(SEQ / QROWS, BATCH * NHEAD), 256, ATT_SMEM>>>(qkv, y);

    // 4. out = y @ wpT^T + b_proj
    tf32_gemm_kernel<<<dim3(CDIM / BN, MROWS / BM), 256, GEMM_SMEM>>>(
        y, wpT, b_proj, out, MROWS, CDIM, CDIM);
}

// round 17
// speedup vs baseline: 2.7769x; 1.0070x over previous
#include <cuda_runtime.h>
#include <cuda_bf16.h>
#include <cstdint>

// ---------------- problem constants ----------------
#define BATCH 4
#define SEQ   2048
#define CDIM  1024
#define NHEAD 16
#define HDIM  64
#define C3    (3*CDIM)
#define MROWS (BATCH*SEQ)   // 8192

// ---------------- scratch (device globals: allocation-free) ----------------
__device__ float g_qkv[MROWS * C3];        // [8192, 3072]
__device__ float g_y[MROWS * CDIM];        // [8192, 1024]
__device__ float g_waT[C3 * CDIM];         // w_attn^T [3072,1024]
__device__ float g_wpT[CDIM * CDIM];       // w_proj^T [1024,1024]

// ---------------- helpers ----------------
__device__ __forceinline__ float rna_tf32(float v) {
    uint32_t u;
    asm("cvt.rna.tf32.f32 %0, %1;" : "=r"(u) : "f"(v));
    return __uint_as_float(u);
}

__device__ __forceinline__ uint32_t rna_u32(uint32_t r) {
    uint32_t u;
    asm("cvt.rna.tf32.f32 %0, %1;" : "=r"(u) : "f"(__uint_as_float(r)));
    return u;
}

__device__ __forceinline__ uint32_t smem_u32(const void* p) {
    uint32_t a;
    asm("{ .reg .u64 t; cvta.to.shared.u64 t, %1; cvt.u32.u64 %0, t; }" : "=r"(a) : "l"(p));
    return a;
}

__device__ __forceinline__ void cp_async16(uint32_t s, const void* g) {
    asm volatile("cp.async.cg.shared.global [%0], [%1], 16;" :: "r"(s), "l"(g));
}

__device__ __forceinline__ void ldsm_x4(uint32_t addr, uint32_t& r0, uint32_t& r1,
                                        uint32_t& r2, uint32_t& r3) {
    asm volatile("ldmatrix.sync.aligned.m8n8.x4.shared.b16 {%0,%1,%2,%3}, [%4];"
                 : "=r"(r0), "=r"(r1), "=r"(r2), "=r"(r3) : "r"(addr));
}

__device__ __forceinline__ void mma_tf32(float& c0, float& c1, float& c2, float& c3,
                                         uint32_t a0, uint32_t a1, uint32_t a2, uint32_t a3,
                                         uint32_t b0, uint32_t b1) {
    asm volatile(
        "mma.sync.aligned.m16n8k8.row.col.f32.tf32.tf32.f32 "
        "{%0,%1,%2,%3}, {%4,%5,%6,%7}, {%8,%9}, {%0,%1,%2,%3};"
        : "+f"(c0), "+f"(c1), "+f"(c2), "+f"(c3)
        : "r"(a0), "r"(a1), "r"(a2), "r"(a3), "r"(b0), "r"(b1));
}

// =================================================================
// tf32 mma.sync GEMM: C[M,N] = A[M,K] @ Bt[N,K]^T + bias[N]
// CTA tile 128x256, BK=32, 256 threads (8 warps, 2x4, warp 64x64).
// 3-stage cp.async pipeline; rna-rounding applied in registers.
// (unchanged from R13)
// =================================================================
#define BM 128
#define BN 256
#define BK 32
#define APAD 36
#define TILE_A_BYTES (128 * APAD * 4)
#define TILE_B_BYTES (256 * APAD * 4)
#define STAGE_BYTES (TILE_A_BYTES + TILE_B_BYTES)
#define NSTAGE 3
#define GEMM_SMEM (NSTAGE * STAGE_BYTES)

__global__ __launch_bounds__(256, 1) void tf32_gemm_kernel(
    const float* __restrict__ A, const float* __restrict__ Bt,
    const float* __restrict__ bias, float* __restrict__ C,
    int M, int N, int K)
{
    extern __shared__ __align__(128) char smem_raw[];
    const uint32_t sbase = smem_u32(smem_raw);

    const int tid = threadIdx.x;
    const int wid = tid >> 5, lane = tid & 31;
    const int warp_m = wid >> 2;
    const int warp_n = wid & 3;
    const int m0 = blockIdx.y * BM;
    const int n0 = blockIdx.x * BN;

    uint32_t sa_off[4], sb_off[8];
    const float* gA[4];
    const float* gB[8];
    #pragma unroll
    for (int i = 0; i < 4; ++i) {
        const int u = tid + 256 * i;
        const int row = u >> 3, cc = u & 7;
        sa_off[i] = (uint32_t)(row * APAD + cc * 4) * 4;
        gA[i] = A + (size_t)(m0 + row) * K + cc * 4;
    }
    #pragma unroll
    for (int i = 0; i < 8; ++i) {
        const int u = tid + 256 * i;
        const int row = u >> 3, cc = u & 7;
        sb_off[i] = (uint32_t)TILE_A_BYTES + (uint32_t)(row * APAD + cc * 4) * 4;
        gB[i] = Bt + (size_t)(n0 + row) * K + cc * 4;
    }

    uint32_t a_off[4];
    {
        const int r = (lane & 7) + ((lane >> 3) & 1) * 8;
        const int cg = (lane >> 4) * 4;
        #pragma unroll
        for (int i = 0; i < 4; ++i)
            a_off[i] = (uint32_t)((warp_m * 64 + 16 * i + r) * APAD + cg) * 4;
    }
    uint32_t b_off[4];
    {
        const int r = (lane & 7) + ((lane >> 4) & 1) * 8;
        const int cg = ((lane >> 3) & 1) * 4;
        #pragma unroll
        for (int p = 0; p < 4; ++p)
            b_off[p] = (uint32_t)TILE_A_BYTES +
                       (uint32_t)((warp_n * 64 + 16 * p + r) * APAD + cg) * 4;
    }

    float acc[4][8][4];
    #pragma unroll
    for (int i = 0; i < 4; ++i)
        #pragma unroll
        for (int j = 0; j < 8; ++j)
            #pragma unroll
            for (int q = 0; q < 4; ++q) acc[i][j][q] = 0.f;

    const int NT = K / BK;

    auto load_stage = [&](int t) {
        const uint32_t sb = sbase + (t % NSTAGE) * STAGE_BYTES;
        #pragma unroll
        for (int i = 0; i < 4; ++i) cp_async16(sb + sa_off[i], gA[i] + t * BK);
        #pragma unroll
        for (int i = 0; i < 8; ++i) cp_async16(sb + sb_off[i], gB[i] + t * BK);
    };

    load_stage(0);
    asm volatile("cp.async.commit_group;");
    load_stage(1);
    asm volatile("cp.async.commit_group;");

    for (int t = 0; t < NT; ++t) {
        asm volatile("cp.async.wait_group 1;");
        __syncthreads();

        if (t + 2 < NT) load_stage(t + 2);
        asm volatile("cp.async.commit_group;");

        const uint32_t st = sbase + (t % NSTAGE) * STAGE_BYTES;
        #pragma unroll
        for (int ks = 0; ks < 4; ++ks) {
            const uint32_t ko = (uint32_t)(ks * 32);
            uint32_t af[4][4], bfr[8][2];
            #pragma unroll
            for (int i = 0; i < 4; ++i) {
                ldsm_x4(st + a_off[i] + ko, af[i][0], af[i][1], af[i][2], af[i][3]);
                af[i][0] = rna_u32(af[i][0]); af[i][1] = rna_u32(af[i][1]);
                af[i][2] = rna_u32(af[i][2]); af[i][3] = rna_u32(af[i][3]);
            }
            #pragma unroll
            for (int p = 0; p < 4; ++p) {
                ldsm_x4(st + b_off[p] + ko,
                        bfr[2*p][0], bfr[2*p][1], bfr[2*p+1][0], bfr[2*p+1][1]);
                bfr[2*p][0]   = rna_u32(bfr[2*p][0]);   bfr[2*p][1]   = rna_u32(bfr[2*p][1]);
                bfr[2*p+1][0] = rna_u32(bfr[2*p+1][0]); bfr[2*p+1][1] = rna_u32(bfr[2*p+1][1]);
            }
            #pragma unroll
            for (int i = 0; i < 4; ++i)
                #pragma unroll
                for (int j = 0; j < 8; ++j)
                    mma_tf32(acc[i][j][0], acc[i][j][1], acc[i][j][2], acc[i][j][3],
                             af[i][0], af[i][1], af[i][2], af[i][3],
                             bfr[j][0], bfr[j][1]);
        }
    }

    const int g = lane >> 2, c = lane & 3;
    #pragma unroll
    for (int i = 0; i < 4; ++i) {
        const int row_a = m0 + warp_m * 64 + 16 * i + g;
        #pragma unroll
        for (int j = 0; j < 8; ++j) {
            const int col = n0 + warp_n * 64 + 8 * j + 2 * c;
            const float b0 = bias[col], b1 = bias[col + 1];
            float2 v0 = make_float2(acc[i][j][0] + b0, acc[i][j][1] + b1);
            float2 v1 = make_float2(acc[i][j][2] + b0, acc[i][j][3] + b1);
            *(float2*)&C[(size_t)row_a * N + col]       = v0;
            *(float2*)&C[(size_t)(row_a + 8) * N + col] = v1;
        }
    }
}

// =================================================================
// pre-pass: transpose only
// =================================================================
__global__ __launch_bounds__(256) void transpose_kernel(
    const float* __restrict__ in, float* __restrict__ out, int K, int N)
{
    __shared__ float tile[32][33];
    const int k0 = blockIdx.y * 32, n0 = blockIdx.x * 32;
    const int tx = threadIdx.x, ty = threadIdx.y;
    #pragma unroll
    for (int i = 0; i < 32; i += 8)
        tile[ty + i][tx] = in[(size_t)(k0 + ty + i) * N + n0 + tx];
    __syncthreads();
    #pragma unroll
    for (int i = 0; i < 32; i += 8)
        out[(size_t)(n0 + ty + i) * K + k0 + tx] = tile[tx][ty + i];
}

// =================================================================
// Tensor-core flash attention (tf32 mma.sync), fp32 softmax, causal.
// Block: (b,h,128-row q tile), 256 threads / 8 warps; 2 CTAs/SM.
// V-transpose store now bank-conflict-free: each thread owns one hd
// column x 4 kv rows -> 4 coalesced scalar LDG + one float4 STS
// (bank = 4*col mod 32, distinct per 8-thread phase).
// =================================================================
#define FPAD 68
#define QROWS 128
#define SQ_BYTES (QROWS * FPAD * 4)     // 34816
#define SK_BYTES (64 * FPAD * 4)        // 17408
#define ATT_SMEM (SQ_BYTES + 2 * SK_BYTES + SQ_BYTES)   // 104448

__global__ __launch_bounds__(256, 2) void attn_mma_kernel(
    const float* __restrict__ qkv, float* __restrict__ y)
{
    extern __shared__ __align__(16) float sm[];
    float* sQ  = sm;                                  // 128 x 68
    float* sK  = sm + QROWS * FPAD;                   // 64 x 68
    float* sVT = sm + QROWS * FPAD + 64 * FPAD;       // 64 x 68 (hd-major)
    float* sP  = sm + QROWS * FPAD + 2 * 64 * FPAD;   // 128 x 68

    const int tid = threadIdx.x;
    const int wid = tid >> 5, lane = tid & 31;
    const int qt = blockIdx.x;
    const int bh = blockIdx.y;
    const int b = bh >> 4, h = bh & 15;
    const int qbase = qt * QROWS;
    const int rowbase = b * SEQ;

    const uint32_t sbase = smem_u32(sm);

    const int ar  = (lane & 7) + ((lane >> 3) & 1) * 8;
    const int acg = (lane >> 4) * 4;
    const uint32_t aoffQ = sbase + (uint32_t)((wid * 16 + ar) * FPAD + acg) * 4;
    const uint32_t aoffP = sbase + (uint32_t)(SQ_BYTES + 2 * SK_BYTES) +
                           (uint32_t)((wid * 16 + ar) * FPAD + acg) * 4;

    const int br  = (lane & 7) + ((lane >> 4) & 1) * 8;
    const int bcg = ((lane >> 3) & 1) * 4;
    uint32_t boffK[4], boffV[4];
    #pragma unroll
    for (int p = 0; p < 4; ++p) {
        boffK[p] = sbase + (uint32_t)SQ_BYTES +
                   (uint32_t)((16 * p + br) * FPAD + bcg) * 4;
        boffV[p] = sbase + (uint32_t)(SQ_BYTES + SK_BYTES) +
                   (uint32_t)((16 * p + br) * FPAD + bcg) * 4;
    }

    // ---- load Q (scaled by 1/sqrt(hd), rna-rounded): 128 rows ----
    for (int u = tid; u < QROWS * 16; u += 256) {
        const int row = u >> 4, c4 = (u & 15) << 2;
        float4 qv = *(const float4*)&qkv[(size_t)(rowbase + qbase + row) * C3 + h * HDIM + c4];
        float4 o;
        o.x = rna_tf32(qv.x * 0.125f); o.y = rna_tf32(qv.y * 0.125f);
        o.z = rna_tf32(qv.z * 0.125f); o.w = rna_tf32(qv.w * 0.125f);
        *(float4*)&sQ[row * FPAD + c4] = o;
    }

    float m0 = -1e30f, m1 = -1e30f, l0 = 0.f, l1 = 0.f;
    float acc_o[8][4];
    #pragma unroll
    for (int j = 0; j < 8; ++j)
        #pragma unroll
        for (int q = 0; q < 4; ++q) acc_o[j][q] = 0.f;

    const int g = lane >> 2, c = lane & 3;
    const int njt = 2 * qt + 2;

    // V column pointer for the conflict-free transpose path
    const int vcol = tid & 63;             // hd column
    const int vrq  = tid >> 6;             // kv row quad 0..3 (advances by 4)

    for (int jt = 0; jt < njt; ++jt) {
        __syncthreads();

        // ---- load K (K-major): float4 LDG -> float4 STS (conflict-free) ----
        for (int u = tid; u < 64 * 16; u += 256) {
            const int row = u >> 4, c4 = (u & 15) << 2;
            const float* kp = &qkv[(size_t)(rowbase + jt * 64 + row) * C3 + CDIM + h * HDIM + c4];
            float4 kv4 = *(const float4*)kp;
            float4 ko;
            ko.x = rna_tf32(kv4.x); ko.y = rna_tf32(kv4.y);
            ko.z = rna_tf32(kv4.z); ko.w = rna_tf32(kv4.w);
            *(float4*)&sK[row * FPAD + c4] = ko;
        }

        // ---- load V transposed: 4 coalesced scalar LDG + 1 float4 STS ----
        // unit (col, rq): rows 4*rq..4*rq+3, hd column col.
        #pragma unroll
        for (int it = 0; it < 4; ++it) {
            const int rq = vrq + 4 * it;           // 0..15
            const float* vp = &qkv[(size_t)(rowbase + jt * 64 + 4 * rq) * C3
                                   + 2 * CDIM + h * HDIM + vcol];
            float4 vo;
            vo.x = rna_tf32(vp[0]);
            vo.y = rna_tf32(vp[C3]);
            vo.z = rna_tf32(vp[2 * C3]);
            vo.w = rna_tf32(vp[3 * C3]);
            *(float4*)&sVT[vcol * FPAD + 4 * rq] = vo;   // bank = 4*vcol%32: clean
        }
        __syncthreads();

        // ---- S = Q @ K^T ----
        float s[8][4];
        #pragma unroll
        for (int j = 0; j < 8; ++j)
            #pragma unroll
            for (int q = 0; q < 4; ++q) s[j][q] = 0.f;

        #pragma unroll
        for (int ks = 0; ks < 8; ++ks) {
            const uint32_t ko = (uint32_t)(ks * 32);
            uint32_t a0, a1, a2, a3;
            ldsm_x4(aoffQ + ko, a0, a1, a2, a3);
            uint32_t bfr[8][2];
            #pragma unroll
            for (int p = 0; p < 4; ++p)
                ldsm_x4(boffK[p] + ko, bfr[2*p][0], bfr[2*p][1], bfr[2*p+1][0], bfr[2*p+1][1]);
            #pragma unroll
            for (int j = 0; j < 8; ++j)
                mma_tf32(s[j][0], s[j][1], s[j][2], s[j][3],
                         a0, a1, a2, a3, bfr[j][0], bfr[j][1]);
        }

        // ---- causal mask (diagonal tiles: jt >= 2*qt) ----
        if (jt >= 2 * qt) {
            const int cbase = 64 * jt - QROWS * qt;
            const int r0 = wid * 16 + g;
            const int r1 = r0 + 8;
            #pragma unroll
            for (int j = 0; j < 8; ++j) {
                const int col = cbase + 8 * j + 2 * c;
                if (col     > r0) s[j][0] = -1e30f;
                if (col + 1 > r0) s[j][1] = -1e30f;
                if (col     > r1) s[j][2] = -1e30f;
                if (col + 1 > r1) s[j][3] = -1e30f;
            }
        }

        // ---- online softmax (quad-lane row reduction) ----
        float mx0 = -1e30f, mx1 = -1e30f;
        #pragma unroll
        for (int j = 0; j < 8; ++j) {
            mx0 = fmaxf(mx0, fmaxf(s[j][0], s[j][1]));
            mx1 = fmaxf(mx1, fmaxf(s[j][2], s[j][3]));
        }
        mx0 = fmaxf(mx0, __shfl_xor_sync(0xffffffffu, mx0, 1));
        mx0 = fmaxf(mx0, __shfl_xor_sync(0xffffffffu, mx0, 2));
        mx1 = fmaxf(mx1, __shfl_xor_sync(0xffffffffu, mx1, 1));
        mx1 = fmaxf(mx1, __shfl_xor_sync(0xffffffffu, mx1, 2));

        const float mn0 = fmaxf(m0, mx0), mn1 = fmaxf(m1, mx1);
        const float corr0 = __expf(m0 - mn0), corr1 = __expf(m1 - mn1);
        float sum0 = 0.f, sum1 = 0.f;
        #pragma unroll
        for (int j = 0; j < 8; ++j) {
            s[j][0] = __expf(s[j][0] - mn0);
            s[j][1] = __expf(s[j][1] - mn0);
            s[j][2] = __expf(s[j][2] - mn1);
            s[j][3] = __expf(s[j][3] - mn1);
            sum0 += s[j][0] + s[j][1];
            sum1 += s[j][2] + s[j][3];
        }
        sum0 += __shfl_xor_sync(0xffffffffu, sum0, 1);
        sum0 += __shfl_xor_sync(0xffffffffu, sum0, 2);
        sum1 += __shfl_xor_sync(0xffffffffu, sum1, 1);
        sum1 += __shfl_xor_sync(0xffffffffu, sum1, 2);

        l0 = l0 * corr0 + sum0;  m0 = mn0;
        l1 = l1 * corr1 + sum1;  m1 = mn1;
        #pragma unroll
        for (int j = 0; j < 8; ++j) {
            acc_o[j][0] *= corr0; acc_o[j][1] *= corr0;
            acc_o[j][2] *= corr1; acc_o[j][3] *= corr1;
        }

        // ---- P -> smem (rna), per-warp-disjoint rows ----
        {
            float* p0 = &sP[(wid * 16 + g) * FPAD + 2 * c];
            float* p1 = &sP[(wid * 16 + 8 + g) * FPAD + 2 * c];
            #pragma unroll
            for (int j = 0; j < 8; ++j) {
                *(float2*)(p0 + 8 * j) = make_float2(rna_tf32(s[j][0]), rna_tf32(s[j][1]));
                *(float2*)(p1 + 8 * j) = make_float2(rna_tf32(s[j][2]), rna_tf32(s[j][3]));
            }
        }
        __syncwarp();

        // ---- O += P @ V ----
        #pragma unroll
        for (int ks = 0; ks < 8; ++ks) {
            const uint32_t ko = (uint32_t)(ks * 32);
            uint32_t a0, a1, a2, a3;
            ldsm_x4(aoffP + ko, a0, a1, a2, a3);
            uint32_t bfr[8][2];
            #pragma unroll
            for (int p = 0; p < 4; ++p)
                ldsm_x4(boffV[p] + ko, bfr[2*p][0], bfr[2*p][1], bfr[2*p+1][0], bfr[2*p+1][1]);
            #pragma unroll
            for (int j = 0; j < 8; ++j)
                mma_tf32(acc_o[j][0], acc_o[j][1], acc_o[j][2], acc_o[j][3],
                         a0, a1, a2, a3, bfr[j][0], bfr[j][1]);
        }
    }

    // ---- finalize + store y ----
    const float inv0 = 1.f / l0, inv1 = 1.f / l1;
    const int grow0 = rowbase + qbase + wid * 16 + g;
    #pragma unroll
    for (int j = 0; j < 8; ++j) {
        const int col = h * HDIM + 8 * j + 2 * c;
        *(float2*)&y[(size_t)grow0 * CDIM + col] =
            make_float2(acc_o[j][0] * inv0, acc_o[j][1] * inv0);
        *(float2*)&y[(size_t)(grow0 + 8) * CDIM + col] =
            make_float2(acc_o[j][2] * inv1, acc_o[j][3] * inv1);
    }
}

// =================================================================
// launch
// =================================================================
extern "C" void kernel_launch(void* const* d_in, const int* in_sizes, int n_in,
                              void* d_out, int out_size)
{
    const float* x      = (const float*)d_in[0];
    const float* w_attn = (const float*)d_in[1];
    const float* b_attn = (const float*)d_in[2];
    const float* w_proj = (const float*)d_in[3];
    const float* b_proj = (const float*)d_in[4];
    float* out = (float*)d_out;

    float *qkv, *y, *waT, *wpT;
    cudaGetSymbolAddress((void**)&qkv, g_qkv);
    cudaGetSymbolAddress((void**)&y,   g_y);
    cudaGetSymbolAddress((void**)&waT, g_waT);
    cudaGetSymbolAddress((void**)&wpT, g_wpT);

    cudaFuncSetAttribute(tf32_gemm_kernel,
                         cudaFuncAttributeMaxDynamicSharedMemorySize, GEMM_SMEM);
    cudaFuncSetAttribute(attn_mma_kernel,
                         cudaFuncAttributeMaxDynamicSharedMemorySize, (int)ATT_SMEM);

    // 1. transpose weights
    transpose_kernel<<<dim3(C3 / 32, CDIM / 32), dim3(32, 8)>>>(w_attn, waT, CDIM, C3);
    transpose_kernel<<<dim3(CDIM / 32, CDIM / 32), dim3(32, 8)>>>(w_proj, wpT, CDIM, CDIM);

    // 2. qkv = x @ waT^T + b_attn
    tf32_gemm_kernel<<<dim3(C3 / BN, MROWS / BM), 256, GEMM_SMEM>>>(
        x, waT, b_attn, qkv, MROWS, C3, CDIM);

    // 3. tensor-core flash attention
    attn_mma_kernel<<<dim3(SEQ / QROWS, BATCH * NHEAD), 256, ATT_SMEM>>>(qkv, y);

    // 4. out = y @ wpT^T + b_proj
    tf32_gemm_kernel<<<dim3(CDIM / BN, MROWS / BM), 256, GEMM_SMEM>>>(
        y, wpT, b_proj, out, MROWS, CDIM, CDIM);
}